// round 13
// baseline (speedup 1.0000x reference)
#include <cuda_runtime.h>
#include <cuda_fp16.h>
#include <cstdint>
#include <math.h>

// Problem constants
#define BB  2
#define LL  1024
#define DD  1024
#define NLAYER 8
#define FF  4096
#define TT  2048          // B*L
#define D3  3072          // 3*D

// weight-buffer layout (halfs per layer)
#define OFF_QKV  0
#define OFF_OUT  3145728
#define OFF_FFN1 4194304
#define OFF_FFN2 8388608
#define LSTRIDE  12582912
#define TILES_PER_LAYER 12288   // 3072 + 1024 + 4096 + 4096

// ---------------- scratch (static device globals; no allocation) ----------------
__device__ float g_x   [TT * DD];
__device__ float g_y   [TT * DD];
__device__ __align__(256) __half g_xh[(size_t)TT * DD];
__device__ __align__(256) __half g_xl[(size_t)TT * DD];
__device__ __align__(256) __half g_oh[(size_t)TT * DD];
__device__ __align__(256) __half g_ol[(size_t)TT * DD];
__device__ __align__(256) __half g_hh[(size_t)TT * FF];
__device__ __align__(256) __half g_hl[(size_t)TT * FF];
__device__ __align__(256) __half g_qh[(size_t)TT * DD];
__device__ __align__(256) __half g_ql[(size_t)TT * DD];
__device__ __align__(256) __half g_kh[(size_t)TT * DD];
__device__ __align__(256) __half g_vh[(size_t)TT * DD];
__device__ __align__(256) __half g_wall[(size_t)NLAYER * LSTRIDE];

// ============================ PTX helpers ============================
__device__ __forceinline__ uint32_t smem_u32(const void* p) {
    uint32_t a;
    asm("{ .reg .u64 t; cvta.to.shared.u64 t, %1; cvt.u32.u64 %0, t; }" : "=r"(a) : "l"(p));
    return a;
}
__device__ __forceinline__ void cp16(uint32_t dst, const void* src) {
    asm volatile("cp.async.cg.shared.global [%0], [%1], 16;" :: "r"(dst), "l"(src));
}
__device__ __forceinline__ void cp_commit() { asm volatile("cp.async.commit_group;" ::: "memory"); }
__device__ __forceinline__ void cp_wait0()  { asm volatile("cp.async.wait_group 0;" ::: "memory"); }
__device__ __forceinline__ void cp_wait1()  { asm volatile("cp.async.wait_group 1;" ::: "memory"); }

__device__ __forceinline__ void ldx4(uint32_t& r0, uint32_t& r1, uint32_t& r2, uint32_t& r3, uint32_t addr) {
    asm volatile("ldmatrix.sync.aligned.m8n8.x4.shared.b16 {%0,%1,%2,%3}, [%4];"
                 : "=r"(r0), "=r"(r1), "=r"(r2), "=r"(r3) : "r"(addr));
}
__device__ __forceinline__ void ldx4t(uint32_t& r0, uint32_t& r1, uint32_t& r2, uint32_t& r3, uint32_t addr) {
    asm volatile("ldmatrix.sync.aligned.m8n8.x4.trans.shared.b16 {%0,%1,%2,%3}, [%4];"
                 : "=r"(r0), "=r"(r1), "=r"(r2), "=r"(r3) : "r"(addr));
}
__device__ __forceinline__ void mma_fp16(float* c, const uint32_t* a, uint32_t b0, uint32_t b1) {
    asm volatile("mma.sync.aligned.m16n8k16.row.col.f32.f16.f16.f32 "
                 "{%0,%1,%2,%3}, {%4,%5,%6,%7}, {%8,%9}, {%0,%1,%2,%3};"
                 : "+f"(c[0]), "+f"(c[1]), "+f"(c[2]), "+f"(c[3])
                 : "r"(a[0]), "r"(a[1]), "r"(a[2]), "r"(a[3]), "r"(b0), "r"(b1));
}
__device__ __forceinline__ uint32_t pk2(__half x, __half y) {
    __half2 h = __halves2half2(x, y);
    return *(uint32_t*)&h;
}
__device__ __forceinline__ uint32_t split2(float x, float y, uint32_t& lo) {
    __half hx = __float2half_rn(x), hy = __float2half_rn(y);
    lo = pk2(__float2half_rn(x - __half2float(hx)), __float2half_rn(y - __half2float(hy)));
    return pk2(hx, hy);
}

// ============================ tensor GEMM 128x128 (fp16 2-term, 8 warps x 32x64, 3-stage) ============================
// mode 1: (Ch,Cl) fp16 planes, with relu
// mode 2: qkv split -> g_qh/g_ql (x0.125), g_kh, g_vh (segment by colBase)
#define MP_STR   40
#define MP_ROWB  (MP_STR * 2)
#define MP_TILE  (128 * MP_ROWB)
#define MP_BUF   (3 * MP_TILE)
#define SMEM_REQ (3 * MP_BUF)

__global__ void __launch_bounds__(256, 2) tgemm_kernel(
    const __half* __restrict__ Ah,
    const __half* __restrict__ Al,
    const __half* __restrict__ Bh,
    const float* __restrict__ bias,
    __half* __restrict__ Ch,
    __half* __restrict__ Cl,
    int M, int N, int K, int relu, int mode)
{
    extern __shared__ char smem[];
    uint32_t sb = smem_u32(smem);
    int tid = threadIdx.x;
    int wid = tid >> 5, lane = tid & 31;
    int wm = (wid & 3) * 32;
    int wn = (wid >> 2) * 64;
    const int rowBase = blockIdx.y * 128;
    const int colBase = blockIdx.x * 128;
    const int nkb = K / 32;

    float acc[2][8][4];
    #pragma unroll
    for (int i = 0; i < 2; i++)
        #pragma unroll
        for (int j = 0; j < 8; j++)
            #pragma unroll
            for (int r = 0; r < 4; r++) acc[i][j][r] = 0.f;

    const int lrow = tid >> 1;
    const int lc = (tid & 1) * 16;

    auto loadTile = [&](int kb, int st) {
        uint32_t db = sb + st * MP_BUF;
        uint32_t doff = lrow * MP_ROWB + lc * 2;
        const __half* pAh = Ah + (size_t)(rowBase + lrow) * K + kb * 32 + lc;
        const __half* pAl = Al + (size_t)(rowBase + lrow) * K + kb * 32 + lc;
        const __half* pBh = Bh + (size_t)(colBase + lrow) * K + kb * 32 + lc;
        cp16(db + 0 * MP_TILE + doff,      pAh);     cp16(db + 0 * MP_TILE + doff + 16, pAh + 8);
        cp16(db + 1 * MP_TILE + doff,      pAl);     cp16(db + 1 * MP_TILE + doff + 16, pAl + 8);
        cp16(db + 2 * MP_TILE + doff,      pBh);     cp16(db + 2 * MP_TILE + doff + 16, pBh + 8);
    };

    loadTile(0, 0);
    cp_commit();
    loadTile(1, 1);
    cp_commit();

    int st = 0, ld = 2;
    for (int kb = 0; kb < nkb; kb++) {
        if (kb + 1 < nkb) cp_wait1(); else cp_wait0();
        __syncthreads();
        if (kb + 2 < nkb) { loadTile(kb + 2, ld); cp_commit(); }

        uint32_t ab = sb + st * MP_BUF;
        uint32_t lb = ab + MP_TILE;
        uint32_t hb = ab + 2 * MP_TILE;

        #pragma unroll
        for (int kk = 0; kk < 2; kk++) {
            int k0 = kk * 16;
            uint32_t aoff = (uint32_t)(wm + (lane & 15)) * MP_ROWB + (k0 + (lane >> 4) * 8) * 2;
            uint32_t ah[2][4], al[2][4];
            #pragma unroll
            for (int mi = 0; mi < 2; mi++) {
                ldx4(ah[mi][0], ah[mi][1], ah[mi][2], ah[mi][3], ab + aoff + mi * 16 * MP_ROWB);
                ldx4(al[mi][0], al[mi][1], al[mi][2], al[mi][3], lb + aoff + mi * 16 * MP_ROWB);
            }
            uint32_t bh[16];
            uint32_t boff = (uint32_t)(wn + ((lane >> 4) * 8) + (lane & 7)) * MP_ROWB
                          + (k0 + ((lane >> 3) & 1) * 8) * 2;
            #pragma unroll
            for (int j = 0; j < 4; j++)
                ldx4(bh[4 * j], bh[4 * j + 1], bh[4 * j + 2], bh[4 * j + 3],
                     hb + boff + (uint32_t)(j * 16) * MP_ROWB);

            #pragma unroll
            for (int mi = 0; mi < 2; mi++)
                #pragma unroll
                for (int ni = 0; ni < 8; ni++) {
                    mma_fp16(acc[mi][ni], ah[mi], bh[2 * ni], bh[2 * ni + 1]);
                    mma_fp16(acc[mi][ni], al[mi], bh[2 * ni], bh[2 * ni + 1]);
                }
        }
        st = (st == 2) ? 0 : st + 1;
        ld = (ld == 2) ? 0 : ld + 1;
    }

    int g = lane >> 2, t = lane & 3;
    const int seg = colBase >> 10;
    #pragma unroll
    for (int mi = 0; mi < 2; mi++) {
        #pragma unroll
        for (int ni = 0; ni < 8; ni++) {
            int m = rowBase + wm + mi * 16 + g;
            int n = colBase + wn + ni * 8 + 2 * t;
            float b0 = bias[n], b1 = bias[n + 1];
            float x0 = acc[mi][ni][0] + b0, y0 = acc[mi][ni][1] + b1;
            float x1 = acc[mi][ni][2] + b0, y1 = acc[mi][ni][3] + b1;
            if (mode == 1) {
                if (relu) {
                    x0 = fmaxf(x0, 0.f); y0 = fmaxf(y0, 0.f);
                    x1 = fmaxf(x1, 0.f); y1 = fmaxf(y1, 0.f);
                }
                size_t o0 = (size_t)m * N + n;
                size_t o1 = (size_t)(m + 8) * N + n;
                uint32_t lo0, lo1;
                uint32_t hi0 = split2(x0, y0, lo0);
                uint32_t hi1 = split2(x1, y1, lo1);
                *(uint32_t*)&Ch[o0] = hi0;  *(uint32_t*)&Cl[o0] = lo0;
                *(uint32_t*)&Ch[o1] = hi1;  *(uint32_t*)&Cl[o1] = lo1;
            } else {
                int nc = n & 1023;
                size_t o0 = (size_t)m * DD + nc;
                size_t o1 = (size_t)(m + 8) * DD + nc;
                if (seg == 0) {
                    uint32_t lo0, lo1;
                    uint32_t hi0 = split2(x0 * 0.125f, y0 * 0.125f, lo0);
                    uint32_t hi1 = split2(x1 * 0.125f, y1 * 0.125f, lo1);
                    *(uint32_t*)&g_qh[o0] = hi0;  *(uint32_t*)&g_ql[o0] = lo0;
                    *(uint32_t*)&g_qh[o1] = hi1;  *(uint32_t*)&g_ql[o1] = lo1;
                } else if (seg == 1) {
                    *(uint32_t*)&g_kh[o0] = pk2(__float2half_rn(x0), __float2half_rn(y0));
                    *(uint32_t*)&g_kh[o1] = pk2(__float2half_rn(x1), __float2half_rn(y1));
                } else {
                    *(uint32_t*)&g_vh[o0] = pk2(__float2half_rn(x0), __float2half_rn(y0));
                    *(uint32_t*)&g_vh[o1] = pk2(__float2half_rn(x1), __float2half_rn(y1));
                }
            }
        }
    }
}

// ============================ tensor GEMM 128x64 (mode-0 only: fp32 out) ============================
#define M6_ATILE (128 * MP_ROWB)
#define M6_BTILE (64 * MP_ROWB)
#define M6_BUF   (2 * M6_ATILE + M6_BTILE)
#define SMEM64   (3 * M6_BUF)

__global__ void __launch_bounds__(256, 2) tgemm64_kernel(
    const __half* __restrict__ Ah,
    const __half* __restrict__ Al,
    const __half* __restrict__ Bh,
    const float* __restrict__ bias,
    float* __restrict__ Cf,
    int M, int N, int K)
{
    extern __shared__ char smem[];
    uint32_t sb = smem_u32(smem);
    int tid = threadIdx.x;
    int wid = tid >> 5, lane = tid & 31;
    int wm = (wid & 3) * 32;
    int wn = (wid >> 2) * 32;
    const int rowBase = blockIdx.y * 128;
    const int colBase = blockIdx.x * 64;
    const int nkb = K / 32;

    float acc[2][4][4];
    #pragma unroll
    for (int i = 0; i < 2; i++)
        #pragma unroll
        for (int j = 0; j < 4; j++)
            #pragma unroll
            for (int r = 0; r < 4; r++) acc[i][j][r] = 0.f;

    const int lrow = tid >> 1;
    const int lc = (tid & 1) * 16;

    auto loadTile = [&](int kb, int st) {
        uint32_t db = sb + st * M6_BUF;
        uint32_t doff = lrow * MP_ROWB + lc * 2;
        const __half* pAh = Ah + (size_t)(rowBase + lrow) * K + kb * 32 + lc;
        const __half* pAl = Al + (size_t)(rowBase + lrow) * K + kb * 32 + lc;
        cp16(db + doff,              pAh);  cp16(db + doff + 16,              pAh + 8);
        cp16(db + M6_ATILE + doff,   pAl);  cp16(db + M6_ATILE + doff + 16,   pAl + 8);
        if (lrow < 64) {
            const __half* pBh = Bh + (size_t)(colBase + lrow) * K + kb * 32 + lc;
            cp16(db + 2 * M6_ATILE + doff, pBh);
            cp16(db + 2 * M6_ATILE + doff + 16, pBh + 8);
        }
    };

    loadTile(0, 0);
    cp_commit();
    loadTile(1, 1);
    cp_commit();

    int st = 0, ld = 2;
    for (int kb = 0; kb < nkb; kb++) {
        if (kb + 1 < nkb) cp_wait1(); else cp_wait0();
        __syncthreads();
        if (kb + 2 < nkb) { loadTile(kb + 2, ld); cp_commit(); }

        uint32_t ab = sb + st * M6_BUF;
        uint32_t lb = ab + M6_ATILE;
        uint32_t hb = ab + 2 * M6_ATILE;

        #pragma unroll
        for (int kk = 0; kk < 2; kk++) {
            int k0 = kk * 16;
            uint32_t aoff = (uint32_t)(wm + (lane & 15)) * MP_ROWB + (k0 + (lane >> 4) * 8) * 2;
            uint32_t ah[2][4], al[2][4];
            #pragma unroll
            for (int mi = 0; mi < 2; mi++) {
                ldx4(ah[mi][0], ah[mi][1], ah[mi][2], ah[mi][3], ab + aoff + mi * 16 * MP_ROWB);
                ldx4(al[mi][0], al[mi][1], al[mi][2], al[mi][3], lb + aoff + mi * 16 * MP_ROWB);
            }
            uint32_t bh[8];
            uint32_t boff = (uint32_t)(wn + ((lane >> 4) * 8) + (lane & 7)) * MP_ROWB
                          + (k0 + ((lane >> 3) & 1) * 8) * 2;
            ldx4(bh[0], bh[1], bh[2], bh[3], hb + boff);
            ldx4(bh[4], bh[5], bh[6], bh[7], hb + boff + 16 * MP_ROWB);

            #pragma unroll
            for (int mi = 0; mi < 2; mi++)
                #pragma unroll
                for (int ni = 0; ni < 4; ni++) {
                    mma_fp16(acc[mi][ni], ah[mi], bh[2 * ni], bh[2 * ni + 1]);
                    mma_fp16(acc[mi][ni], al[mi], bh[2 * ni], bh[2 * ni + 1]);
                }
        }
        st = (st == 2) ? 0 : st + 1;
        ld = (ld == 2) ? 0 : ld + 1;
    }

    int g = lane >> 2, t = lane & 3;
    #pragma unroll
    for (int mi = 0; mi < 2; mi++) {
        #pragma unroll
        for (int ni = 0; ni < 4; ni++) {
            int m = rowBase + wm + mi * 16 + g;
            int n = colBase + wn + ni * 8 + 2 * t;
            float b0 = bias[n], b1 = bias[n + 1];
            size_t o0 = (size_t)m * N + n;
            size_t o1 = (size_t)(m + 8) * N + n;
            *(float2*)&Cf[o0] = make_float2(acc[mi][ni][0] + b0, acc[mi][ni][1] + b1);
            *(float2*)&Cf[o1] = make_float2(acc[mi][ni][2] + b0, acc[mi][ni][3] + b1);
        }
    }
}

// ============================ flash attention v2 (2-pass S, compact smem, 2 CTAs/SM) ============================
#define FA_STR   72
#define FA_ROWB  144
#define FA_TILE  (128 * FA_ROWB)
#define FA_SMEM2 (4 * FA_TILE)        // 73728: [KV0: K,V][KV1: K,V] ; Q staged in KV1

__global__ void __launch_bounds__(256, 2) flash_kernel(
    const __half* __restrict__ Qh, const __half* __restrict__ Ql,
    const __half* __restrict__ Kh, const __half* __restrict__ Vh,
    __half* __restrict__ Oh, __half* __restrict__ Ol)
{
    extern __shared__ char smem[];
    uint32_t sb = smem_u32(smem);
    const int bh = blockIdx.x;
    const int qt = 7 - blockIdx.y;
    const int b = bh >> 4, h = bh & 15;
    const int tid = threadIdx.x, wid = tid >> 5, lane = tid & 31;
    const int g = lane >> 2, t4 = lane & 3;
    const int wq = wid * 16 + g;

    const uint32_t kv0 = sb;
    const uint32_t kv1 = sb + 2 * FA_TILE;
    const size_t colbase = (size_t)h * 64;

    // stage Q into kv1 (Qh at kv1, Ql at kv1+FA_TILE); K0/V0 into kv0
    {
        int qrow0 = b * LL + qt * 128;
        int krow0 = b * LL;
        #pragma unroll
        for (int i = 0; i < 4; i++) {
            int ch = tid + i * 256;
            int row = ch >> 3, cc = ch & 7;
            uint32_t so = row * FA_ROWB + cc * 16;
            size_t qo = (size_t)(qrow0 + row) * DD + colbase + cc * 8;
            size_t ko = (size_t)(krow0 + row) * DD + colbase + cc * 8;
            cp16(kv1 + so, Qh + qo);
            cp16(kv1 + FA_TILE + so, Ql + qo);
            cp16(kv0 + so, Kh + ko);
            cp16(kv0 + FA_TILE + so, Vh + ko);
        }
        cp_commit();
    }
    cp_wait0();
    __syncthreads();

    // extract Q fragments; kv1 is dead afterwards (guarded by loop-head sync)
    uint32_t qhf[4][4], qlf[4][4];
    {
        uint32_t arow = (uint32_t)(wid * 16 + (lane & 15)) * FA_ROWB;
        #pragma unroll
        for (int kk = 0; kk < 4; kk++) {
            uint32_t aoff = arow + (kk * 16 + (lane >> 4) * 8) * 2;
            ldx4(qhf[kk][0], qhf[kk][1], qhf[kk][2], qhf[kk][3], kv1 + aoff);
            ldx4(qlf[kk][0], qlf[kk][1], qlf[kk][2], qlf[kk][3], kv1 + FA_TILE + aoff);
        }
    }

    float oacc[8][4];
    #pragma unroll
    for (int i = 0; i < 8; i++)
        #pragma unroll
        for (int j = 0; j < 4; j++) oacc[i][j] = 0.f;
    float m0 = -1e30f, m1 = -1e30f, l0 = 0.f, l1 = 0.f;

    for (int kt = 0; kt <= qt; kt++) {
        int buf = kt & 1;
        __syncthreads();                       // all warps done with prev buffer (and Q frags extracted)
        if (kt < qt) {
            int krow0 = b * LL + (kt + 1) * 128;
            uint32_t dstK = (buf == 0) ? kv1 : kv0;
            #pragma unroll
            for (int i = 0; i < 4; i++) {
                int ch = tid + i * 256;
                int row = ch >> 3, cc = ch & 7;
                uint32_t so = row * FA_ROWB + cc * 16;
                size_t ko = (size_t)(krow0 + row) * DD + colbase + cc * 8;
                cp16(dstK + so, Kh + ko);
                cp16(dstK + FA_TILE + so, Vh + ko);
            }
            cp_commit();
            cp_wait1();
        } else {
            cp_wait0();
        }
        __syncthreads();

        uint32_t kb = (buf == 0) ? kv0 : kv1;
        uint32_t vb = kb + FA_TILE;

        // two 64-column passes over this kt tile
        #pragma unroll
        for (int p = 0; p < 2; p++) {
            float s[8][4];
            #pragma unroll
            for (int i = 0; i < 8; i++)
                #pragma unroll
                for (int j = 0; j < 4; j++) s[i][j] = 0.f;

            #pragma unroll
            for (int kk = 0; kk < 4; kk++) {
                #pragma unroll
                for (int nj = 0; nj < 4; nj++) {
                    uint32_t boff = kb + (uint32_t)(p * 64 + nj * 16 + (lane >> 4) * 8 + (lane & 7)) * FA_ROWB
                                  + (kk * 16 + ((lane >> 3) & 1) * 8) * 2;
                    uint32_t b0, b1, b2, b3;
                    ldx4(b0, b1, b2, b3, boff);
                    mma_fp16(s[2 * nj],     qhf[kk], b0, b1);
                    mma_fp16(s[2 * nj],     qlf[kk], b0, b1);
                    mma_fp16(s[2 * nj + 1], qhf[kk], b2, b3);
                    mma_fp16(s[2 * nj + 1], qlf[kk], b2, b3);
                }
            }

            // causal mask (diagonal tile only; local row wq vs local col)
            if (kt == qt) {
                #pragma unroll
                for (int ni = 0; ni < 8; ni++) {
                    int cl = p * 64 + ni * 8 + t4 * 2;
                    if (cl     > wq)     s[ni][0] = -1e30f;
                    if (cl + 1 > wq)     s[ni][1] = -1e30f;
                    if (cl     > wq + 8) s[ni][2] = -1e30f;
                    if (cl + 1 > wq + 8) s[ni][3] = -1e30f;
                }
            }

            float mx0 = -1e30f, mx1 = -1e30f;
            #pragma unroll
            for (int ni = 0; ni < 8; ni++) {
                mx0 = fmaxf(mx0, fmaxf(s[ni][0], s[ni][1]));
                mx1 = fmaxf(mx1, fmaxf(s[ni][2], s[ni][3]));
            }
            mx0 = fmaxf(mx0, __shfl_xor_sync(0xffffffffu, mx0, 1));
            mx0 = fmaxf(mx0, __shfl_xor_sync(0xffffffffu, mx0, 2));
            mx1 = fmaxf(mx1, __shfl_xor_sync(0xffffffffu, mx1, 1));
            mx1 = fmaxf(mx1, __shfl_xor_sync(0xffffffffu, mx1, 2));
            float nm0 = fmaxf(m0, mx0), nm1 = fmaxf(m1, mx1);
            float f0 = __expf(m0 - nm0), f1 = __expf(m1 - nm1);

            float sum0 = 0.f, sum1 = 0.f;
            #pragma unroll
            for (int ni = 0; ni < 8; ni++) {
                s[ni][0] = __expf(s[ni][0] - nm0);
                s[ni][1] = __expf(s[ni][1] - nm0);
                s[ni][2] = __expf(s[ni][2] - nm1);
                s[ni][3] = __expf(s[ni][3] - nm1);
                sum0 += s[ni][0] + s[ni][1];
                sum1 += s[ni][2] + s[ni][3];
            }
            sum0 += __shfl_xor_sync(0xffffffffu, sum0, 1);
            sum0 += __shfl_xor_sync(0xffffffffu, sum0, 2);
            sum1 += __shfl_xor_sync(0xffffffffu, sum1, 1);
            sum1 += __shfl_xor_sync(0xffffffffu, sum1, 2);
            l0 = l0 * f0 + sum0;
            l1 = l1 * f1 + sum1;
            m0 = nm0; m1 = nm1;

            #pragma unroll
            for (int dj = 0; dj < 8; dj++) {
                oacc[dj][0] *= f0; oacc[dj][1] *= f0;
                oacc[dj][2] *= f1; oacc[dj][3] *= f1;
            }

            // O += (Ph + Pl) @ V[64 rows of this pass]
            #pragma unroll
            for (int kk = 0; kk < 4; kk++) {
                uint32_t ah[4], al[4];
                ah[0] = split2(s[2 * kk][0],     s[2 * kk][1],     al[0]);
                ah[1] = split2(s[2 * kk][2],     s[2 * kk][3],     al[1]);
                ah[2] = split2(s[2 * kk + 1][0], s[2 * kk + 1][1], al[2]);
                ah[3] = split2(s[2 * kk + 1][2], s[2 * kk + 1][3], al[3]);

                uint32_t vrow = (uint32_t)(p * 64 + kk * 16 + (lane & 7) + 8 * ((lane >> 3) & 1)) * FA_ROWB;
                #pragma unroll
                for (int dj = 0; dj < 4; dj++) {
                    uint32_t r0, r1, r2, r3;
                    ldx4t(r0, r1, r2, r3, vb + vrow + (dj * 16 + (lane >> 4) * 8) * 2);
                    mma_fp16(oacc[2 * dj],     ah, r0, r1);
                    mma_fp16(oacc[2 * dj],     al, r0, r1);
                    mma_fp16(oacc[2 * dj + 1], ah, r2, r3);
                    mma_fp16(oacc[2 * dj + 1], al, r2, r3);
                }
            }
        }
    }

    float i0 = 1.f / l0, i1 = 1.f / l1;
    int q0 = qt * 128 + wq;
    size_t r0o = (size_t)(b * LL + q0) * DD + colbase + t4 * 2;
    size_t r1o = r0o + (size_t)8 * DD;
    #pragma unroll
    for (int dj = 0; dj < 8; dj++) {
        uint32_t lo0, lo1;
        uint32_t hi0 = split2(oacc[dj][0] * i0, oacc[dj][1] * i0, lo0);
        uint32_t hi1 = split2(oacc[dj][2] * i1, oacc[dj][3] * i1, lo1);
        *(uint32_t*)&Oh[r0o + dj * 8] = hi0;  *(uint32_t*)&Ol[r0o + dj * 8] = lo0;
        *(uint32_t*)&Oh[r1o + dj * 8] = hi1;  *(uint32_t*)&Ol[r1o + dj * 8] = lo1;
    }
}

// ============================ convAll ============================
__global__ void __launch_bounds__(256) convAll_kernel(
    const float* __restrict__ qkvW, const float* __restrict__ outW,
    const float* __restrict__ w1,   const float* __restrict__ w2)
{
    int bid = blockIdx.x;
    int layer = bid / TILES_PER_LAYER;
    int r = bid % TILES_PER_LAYER;
    const float* src;
    __half* dst;
    int K, N;
    if (r < 3072) {
        src = qkvW + (size_t)layer * DD * D3;
        dst = g_wall + (size_t)layer * LSTRIDE + OFF_QKV;
        K = DD; N = D3;
    } else if (r < 4096) {
        r -= 3072;
        src = outW + (size_t)layer * DD * DD;
        dst = g_wall + (size_t)layer * LSTRIDE + OFF_OUT;
        K = DD; N = DD;
    } else if (r < 8192) {
        r -= 4096;
        src = w1 + (size_t)layer * DD * FF;
        dst = g_wall + (size_t)layer * LSTRIDE + OFF_FFN1;
        K = DD; N = FF;
    } else {
        r -= 8192;
        src = w2 + (size_t)layer * FF * DD;
        dst = g_wall + (size_t)layer * LSTRIDE + OFF_FFN2;
        K = FF; N = DD;
    }
    int ntx = N / 32;
    int nb = (r % ntx) * 32;
    int kb = (r / ntx) * 32;

    __shared__ float tile[32][33];
    int tid = threadIdx.x;
    int tx = tid & 31, ty = tid >> 5;
    #pragma unroll
    for (int q = 0; q < 4; q++)
        tile[ty + 8 * q][tx] = src[(size_t)(kb + ty + 8 * q) * N + nb + tx];
    __syncthreads();
    #pragma unroll
    for (int q = 0; q < 4; q++) {
        int n = nb + ty + 8 * q;
        int k = kb + tx;
        dst[(size_t)n * K + k] = __float2half_rn(tile[tx][ty + 8 * q]);
    }
}

// ---------------- embedding + input proj + posenc (+ planes) ----------------
__global__ void embed_kernel(const int* __restrict__ card_ids,
                             const int* __restrict__ action_ids,
                             const float* __restrict__ bet,
                             const float* __restrict__ card_tab,
                             const float* __restrict__ action_tab,
                             const float* __restrict__ bet_W,
                             const float* __restrict__ bet_b,
                             const float* __restrict__ in_W,
                             const float* __restrict__ in_b)
{
    int t = blockIdx.x;
    int l = t & (LL - 1);
    __shared__ float tok[48];
    int tid = threadIdx.x;
    if (tid < 16)       tok[tid] = card_tab[card_ids[t] * 16 + tid];
    else if (tid < 32)  tok[tid] = action_tab[action_ids[t] * 16 + (tid - 16)];
    else if (tid < 48)  tok[tid] = bet[t] * bet_W[tid - 32] + bet_b[tid - 32];
    __syncthreads();

    const float cdiv = -9.210340371976184f / 1024.0f;
    for (int d = tid; d < DD; d += 256) {
        float acc = in_b[d];
        #pragma unroll
        for (int c = 0; c < 48; c++) acc += tok[c] * in_W[c * DD + d];
        int j2 = d & ~1;
        float ang = (float)l * expf((float)j2 * cdiv);
        float pe = (d & 1) ? cosf(ang) : sinf(ang);
        float x = acc + pe;
        g_x[t * DD + d] = x;
        __half h = __float2half_rn(x);
        g_xh[(size_t)t * DD + d] = h;
        g_xl[(size_t)t * DD + d] = __float2half_rn(x - __half2float(h));
    }
}

// ---------------- residual add + layernorm (+ planes) ----------------
__global__ void __launch_bounds__(256) ln_kernel(const float* __restrict__ xin,
                                                 const float* __restrict__ delta,
                                                 const float* __restrict__ gamma,
                                                 const float* __restrict__ beta,
                                                 float* __restrict__ out,
                                                 __half* __restrict__ Ch,
                                                 __half* __restrict__ Cl)
{
    int row = blockIdx.x, tid = threadIdx.x, lane = tid & 31, warp = tid >> 5;
    __shared__ float red1[8];
    __shared__ float red2[8];
    __shared__ float stats[2];

    float v[4];
    float s = 0.f, s2 = 0.f;
    #pragma unroll
    for (int r = 0; r < 4; r++) {
        int d = tid + r * 256;
        float x = xin[(size_t)row * DD + d] + delta[(size_t)row * DD + d];
        v[r] = x; s += x; s2 += x * x;
    }
    #pragma unroll
    for (int o = 16; o > 0; o >>= 1) {
        s  += __shfl_xor_sync(0xffffffffu, s, o);
        s2 += __shfl_xor_sync(0xffffffffu, s2, o);
    }
    if (lane == 0) { red1[warp] = s; red2[warp] = s2; }
    __syncthreads();
    if (tid == 0) {
        float a = 0.f, c = 0.f;
        #pragma unroll
        for (int i = 0; i < 8; i++) { a += red1[i]; c += red2[i]; }
        float mu = a * (1.0f / DD);
        float var = c * (1.0f / DD) - mu * mu;
        stats[0] = mu;
        stats[1] = rsqrtf(var + 1e-5f);
    }
    __syncthreads();
    float mu = stats[0], rstd = stats[1];
    #pragma unroll
    for (int r = 0; r < 4; r++) {
        int d = tid + r * 256;
        float y = (v[r] - mu) * rstd * gamma[d] + beta[d];
        out[(size_t)row * DD + d] = y;
        __half h = __float2half_rn(y);
        Ch[(size_t)row * DD + d] = h;
        Cl[(size_t)row * DD + d] = __float2half_rn(y - __half2float(h));
    }
}

// ---------------- extract x[:, -1] ----------------
__global__ void final_kernel(float* __restrict__ out)
{
    int b = blockIdx.x;
    int d = blockIdx.y * 256 + threadIdx.x;
    out[b * DD + d] = g_x[(size_t)(b * LL + (LL - 1)) * DD + d];
}

// ---------------- host launch ----------------
extern "C" void kernel_launch(void* const* d_in, const int* in_sizes, int n_in,
                              void* d_out, int out_size)
{
    const int*   card_ids   = (const int*)  d_in[0];
    const int*   action_ids = (const int*)  d_in[1];
    const float* bet        = (const float*)d_in[2];
    const float* card_tab   = (const float*)d_in[3];
    const float* action_tab = (const float*)d_in[4];
    const float* bet_W      = (const float*)d_in[5];
    const float* bet_b      = (const float*)d_in[6];
    const float* in_W       = (const float*)d_in[7];
    const float* in_b       = (const float*)d_in[8];
    const float* qkv_W      = (const float*)d_in[9];
    const float* qkv_b      = (const float*)d_in[10];
    const float* out_W      = (const float*)d_in[11];
    const float* out_b      = (const float*)d_in[12];
    const float* ln1_g      = (const float*)d_in[13];
    const float* ln1_b      = (const float*)d_in[14];
    const float* ffn_W1     = (const float*)d_in[15];
    const float* ffn_b1     = (const float*)d_in[16];
    const float* ffn_W2     = (const float*)d_in[17];
    const float* ffn_b2     = (const float*)d_in[18];
    const float* ln2_g      = (const float*)d_in[19];
    const float* ln2_b      = (const float*)d_in[20];

    float *px, *py;
    __half *pxh, *pxl, *poh, *pol, *phh, *phl, *pqh, *pql, *pkh, *pvh, *pwall;
    cudaGetSymbolAddress((void**)&px,    g_x);
    cudaGetSymbolAddress((void**)&py,    g_y);
    cudaGetSymbolAddress((void**)&pxh,   g_xh);
    cudaGetSymbolAddress((void**)&pxl,   g_xl);
    cudaGetSymbolAddress((void**)&poh,   g_oh);
    cudaGetSymbolAddress((void**)&pol,   g_ol);
    cudaGetSymbolAddress((void**)&phh,   g_hh);
    cudaGetSymbolAddress((void**)&phl,   g_hl);
    cudaGetSymbolAddress((void**)&pqh,   g_qh);
    cudaGetSymbolAddress((void**)&pql,   g_ql);
    cudaGetSymbolAddress((void**)&pkh,   g_kh);
    cudaGetSymbolAddress((void**)&pvh,   g_vh);
    cudaGetSymbolAddress((void**)&pwall, g_wall);

    static int configured = 0;
    if (!configured) {
        cudaFuncSetAttribute(tgemm_kernel,   cudaFuncAttributeMaxDynamicSharedMemorySize, SMEM_REQ);
        cudaFuncSetAttribute(tgemm64_kernel, cudaFuncAttributeMaxDynamicSharedMemorySize, SMEM64);
        cudaFuncSetAttribute(flash_kernel,   cudaFuncAttributeMaxDynamicSharedMemorySize, FA_SMEM2);
        configured = 1;
    }

    convAll_kernel<<<NLAYER * TILES_PER_LAYER, 256>>>(qkv_W, out_W, ffn_W1, ffn_W2);

    embed_kernel<<<TT, 256>>>(card_ids, action_ids, bet, card_tab, action_tab,
                              bet_W, bet_b, in_W, in_b);

    for (int i = 0; i < NLAYER; i++) {
        __half* wqkv = pwall + (size_t)i * LSTRIDE + OFF_QKV;
        __half* wout = pwall + (size_t)i * LSTRIDE + OFF_OUT;
        __half* wff1 = pwall + (size_t)i * LSTRIDE + OFF_FFN1;
        __half* wff2 = pwall + (size_t)i * LSTRIDE + OFF_FFN2;
        const float* qkvb_i = qkv_b  + (size_t)i * D3;
        const float* outb_i = out_b  + (size_t)i * DD;
        const float* l1g_i  = ln1_g  + (size_t)i * DD;
        const float* l1b_i  = ln1_b  + (size_t)i * DD;
        const float* b1_i   = ffn_b1 + (size_t)i * FF;
        const float* b2_i   = ffn_b2 + (size_t)i * DD;
        const float* l2g_i  = ln2_g  + (size_t)i * DD;
        const float* l2b_i  = ln2_b  + (size_t)i * DD;

        // qkv projection -> Q/K/V planes (mode 2, 128x128 tiles)
        tgemm_kernel<<<dim3(D3 / 128, TT / 128), 256, SMEM_REQ>>>(
            pxh, pxl, wqkv, qkvb_i, nullptr, nullptr, TT, D3, DD, 0, 2);

        // fused flash attention -> O planes (2 CTAs/SM)
        flash_kernel<<<dim3(32, 8), 256, FA_SMEM2>>>(pqh, pql, pkh, pvh, poh, pol);

        // attn out projection -> fp32 delta (128x64 tiles)
        tgemm64_kernel<<<dim3(DD / 64, TT / 128), 256, SMEM64>>>(
            poh, pol, wout, outb_i, py, TT, DD, DD);

        // x = LN(x + attn)
        ln_kernel<<<TT, 256>>>(px, py, l1g_i, l1b_i, px, pxh, pxl);

        // ffn1 (relu) -> hidden planes (mode 1, 128x128 tiles)
        tgemm_kernel<<<dim3(FF / 128, TT / 128), 256, SMEM_REQ>>>(
            pxh, pxl, wff1, b1_i, phh, phl, TT, FF, DD, 1, 1);

        // ffn2 -> fp32 delta (128x64 tiles)
        tgemm64_kernel<<<dim3(DD / 64, TT / 128), 256, SMEM64>>>(
            phh, phl, wff2, b2_i, py, TT, DD, FF);

        // x = LN(x + ffn)
        ln_kernel<<<TT, 256>>>(px, py, l2g_i, l2b_i, px, pxh, pxl);
    }

    final_kernel<<<dim3(BB, DD / 256), 256>>>((float*)d_out);
}

// round 14
// speedup vs baseline: 1.0335x; 1.0335x over previous
#include <cuda_runtime.h>
#include <cuda_fp16.h>
#include <cstdint>
#include <math.h>

// Problem constants
#define BB  2
#define LL  1024
#define DD  1024
#define NLAYER 8
#define FF  4096
#define TT  2048          // B*L
#define D3  3072          // 3*D

// weight-buffer layout (halfs per layer)
#define OFF_QKV  0
#define OFF_OUT  3145728
#define OFF_FFN1 4194304
#define OFF_FFN2 8388608
#define LSTRIDE  12582912
#define TILES_PER_LAYER 12288   // 3072 + 1024 + 4096 + 4096

// ---------------- scratch (static device globals; no allocation) ----------------
__device__ float g_x   [TT * DD];
__device__ float g_y   [TT * DD];
__device__ __align__(256) __half g_xh[(size_t)TT * DD];
__device__ __align__(256) __half g_xl[(size_t)TT * DD];
__device__ __align__(256) __half g_oh[(size_t)TT * DD];
__device__ __align__(256) __half g_ol[(size_t)TT * DD];
__device__ __align__(256) __half g_hh[(size_t)TT * FF];
__device__ __align__(256) __half g_hl[(size_t)TT * FF];
__device__ __align__(256) __half g_qh[(size_t)TT * DD];
__device__ __align__(256) __half g_ql[(size_t)TT * DD];
__device__ __align__(256) __half g_kh[(size_t)TT * DD];
__device__ __align__(256) __half g_vh[(size_t)TT * DD];
__device__ __align__(256) __half g_wall[(size_t)NLAYER * LSTRIDE];

// ============================ PTX helpers ============================
__device__ __forceinline__ uint32_t smem_u32(const void* p) {
    uint32_t a;
    asm("{ .reg .u64 t; cvta.to.shared.u64 t, %1; cvt.u32.u64 %0, t; }" : "=r"(a) : "l"(p));
    return a;
}
__device__ __forceinline__ void cp16(uint32_t dst, const void* src) {
    asm volatile("cp.async.cg.shared.global [%0], [%1], 16;" :: "r"(dst), "l"(src));
}
__device__ __forceinline__ void cp_commit() { asm volatile("cp.async.commit_group;" ::: "memory"); }
__device__ __forceinline__ void cp_wait0()  { asm volatile("cp.async.wait_group 0;" ::: "memory"); }
__device__ __forceinline__ void cp_wait1()  { asm volatile("cp.async.wait_group 1;" ::: "memory"); }

__device__ __forceinline__ void ldx4(uint32_t& r0, uint32_t& r1, uint32_t& r2, uint32_t& r3, uint32_t addr) {
    asm volatile("ldmatrix.sync.aligned.m8n8.x4.shared.b16 {%0,%1,%2,%3}, [%4];"
                 : "=r"(r0), "=r"(r1), "=r"(r2), "=r"(r3) : "r"(addr));
}
__device__ __forceinline__ void ldx4t(uint32_t& r0, uint32_t& r1, uint32_t& r2, uint32_t& r3, uint32_t addr) {
    asm volatile("ldmatrix.sync.aligned.m8n8.x4.trans.shared.b16 {%0,%1,%2,%3}, [%4];"
                 : "=r"(r0), "=r"(r1), "=r"(r2), "=r"(r3) : "r"(addr));
}
__device__ __forceinline__ void mma_fp16(float* c, const uint32_t* a, uint32_t b0, uint32_t b1) {
    asm volatile("mma.sync.aligned.m16n8k16.row.col.f32.f16.f16.f32 "
                 "{%0,%1,%2,%3}, {%4,%5,%6,%7}, {%8,%9}, {%0,%1,%2,%3};"
                 : "+f"(c[0]), "+f"(c[1]), "+f"(c[2]), "+f"(c[3])
                 : "r"(a[0]), "r"(a[1]), "r"(a[2]), "r"(a[3]), "r"(b0), "r"(b1));
}
__device__ __forceinline__ uint32_t pk2(__half x, __half y) {
    __half2 h = __halves2half2(x, y);
    return *(uint32_t*)&h;
}
__device__ __forceinline__ uint32_t split2(float x, float y, uint32_t& lo) {
    __half hx = __float2half_rn(x), hy = __float2half_rn(y);
    lo = pk2(__float2half_rn(x - __half2float(hx)), __float2half_rn(y - __half2float(hy)));
    return pk2(hx, hy);
}

// ============================ tensor GEMM (fp16 2-term, 8 warps x 32x64, 3-stage) ============================
// mode 0: Cf fp32 = A@B^T + bias
// mode 1: (Ch,Cl) fp16 planes, with relu
// mode 2: qkv split -> g_qh/g_ql (x0.125), g_kh, g_vh (segment by colBase)
#define MP_STR   40
#define MP_ROWB  (MP_STR * 2)
#define MP_TILE  (128 * MP_ROWB)
#define MP_BUF   (3 * MP_TILE)
#define SMEM_REQ (3 * MP_BUF)

__global__ void __launch_bounds__(256, 2) tgemm_kernel(
    const __half* __restrict__ Ah,
    const __half* __restrict__ Al,
    const __half* __restrict__ Bh,
    const float* __restrict__ bias,
    float* __restrict__ Cf,
    __half* __restrict__ Ch,
    __half* __restrict__ Cl,
    int M, int N, int K, int relu, int mode)
{
    extern __shared__ char smem[];
    uint32_t sb = smem_u32(smem);
    int tid = threadIdx.x;
    int wid = tid >> 5, lane = tid & 31;
    int wm = (wid & 3) * 32;             // warp m offset (4 strips of 32)
    int wn = (wid >> 2) * 64;            // warp n offset (2 strips of 64)
    const int rowBase = blockIdx.y * 128;
    const int colBase = blockIdx.x * 128;
    const int nkb = K / 32;

    float acc[2][8][4];
    #pragma unroll
    for (int i = 0; i < 2; i++)
        #pragma unroll
        for (int j = 0; j < 8; j++)
            #pragma unroll
            for (int r = 0; r < 4; r++) acc[i][j][r] = 0.f;

    const int lrow = tid >> 1;
    const int lc = (tid & 1) * 16;

    auto loadTile = [&](int kb, int st) {
        uint32_t db = sb + st * MP_BUF;
        uint32_t doff = lrow * MP_ROWB + lc * 2;
        const __half* pAh = Ah + (size_t)(rowBase + lrow) * K + kb * 32 + lc;
        const __half* pAl = Al + (size_t)(rowBase + lrow) * K + kb * 32 + lc;
        const __half* pBh = Bh + (size_t)(colBase + lrow) * K + kb * 32 + lc;
        cp16(db + 0 * MP_TILE + doff,      pAh);     cp16(db + 0 * MP_TILE + doff + 16, pAh + 8);
        cp16(db + 1 * MP_TILE + doff,      pAl);     cp16(db + 1 * MP_TILE + doff + 16, pAl + 8);
        cp16(db + 2 * MP_TILE + doff,      pBh);     cp16(db + 2 * MP_TILE + doff + 16, pBh + 8);
    };

    loadTile(0, 0);
    cp_commit();
    loadTile(1, 1);
    cp_commit();

    int st = 0, ld = 2;
    for (int kb = 0; kb < nkb; kb++) {
        if (kb + 1 < nkb) cp_wait1(); else cp_wait0();
        __syncthreads();
        if (kb + 2 < nkb) { loadTile(kb + 2, ld); cp_commit(); }

        uint32_t ab = sb + st * MP_BUF;
        uint32_t lb = ab + MP_TILE;
        uint32_t hb = ab + 2 * MP_TILE;

        #pragma unroll
        for (int kk = 0; kk < 2; kk++) {
            int k0 = kk * 16;
            // A fragments: 2 m-strips of 16 rows, 2 planes
            uint32_t aoff = (uint32_t)(wm + (lane & 15)) * MP_ROWB + (k0 + (lane >> 4) * 8) * 2;
            uint32_t ah[2][4], al[2][4];
            #pragma unroll
            for (int mi = 0; mi < 2; mi++) {
                ldx4(ah[mi][0], ah[mi][1], ah[mi][2], ah[mi][3], ab + aoff + mi * 16 * MP_ROWB);
                ldx4(al[mi][0], al[mi][1], al[mi][2], al[mi][3], lb + aoff + mi * 16 * MP_ROWB);
            }
            // B fragments: 64 columns = 4 ldx4 of 16 rows each
            uint32_t bh[16];
            uint32_t boff = (uint32_t)(wn + ((lane >> 4) * 8) + (lane & 7)) * MP_ROWB
                          + (k0 + ((lane >> 3) & 1) * 8) * 2;
            #pragma unroll
            for (int j = 0; j < 4; j++)
                ldx4(bh[4 * j], bh[4 * j + 1], bh[4 * j + 2], bh[4 * j + 3],
                     hb + boff + (uint32_t)(j * 16) * MP_ROWB);

            #pragma unroll
            for (int mi = 0; mi < 2; mi++)
                #pragma unroll
                for (int ni = 0; ni < 8; ni++) {
                    mma_fp16(acc[mi][ni], ah[mi], bh[2 * ni], bh[2 * ni + 1]);
                    mma_fp16(acc[mi][ni], al[mi], bh[2 * ni], bh[2 * ni + 1]);
                }
        }
        st = (st == 2) ? 0 : st + 1;
        ld = (ld == 2) ? 0 : ld + 1;
    }

    int g = lane >> 2, t = lane & 3;
    const int seg = colBase >> 10;            // for mode 2
    #pragma unroll
    for (int mi = 0; mi < 2; mi++) {
        #pragma unroll
        for (int ni = 0; ni < 8; ni++) {
            int m = rowBase + wm + mi * 16 + g;
            int n = colBase + wn + ni * 8 + 2 * t;
            float b0 = bias[n], b1 = bias[n + 1];
            float x0 = acc[mi][ni][0] + b0, y0 = acc[mi][ni][1] + b1;
            float x1 = acc[mi][ni][2] + b0, y1 = acc[mi][ni][3] + b1;
            if (mode == 0) {
                size_t o0 = (size_t)m * N + n;
                size_t o1 = (size_t)(m + 8) * N + n;
                *(float2*)&Cf[o0] = make_float2(x0, y0);
                *(float2*)&Cf[o1] = make_float2(x1, y1);
            } else if (mode == 1) {
                if (relu) {
                    x0 = fmaxf(x0, 0.f); y0 = fmaxf(y0, 0.f);
                    x1 = fmaxf(x1, 0.f); y1 = fmaxf(y1, 0.f);
                }
                size_t o0 = (size_t)m * N + n;
                size_t o1 = (size_t)(m + 8) * N + n;
                uint32_t lo0, lo1;
                uint32_t hi0 = split2(x0, y0, lo0);
                uint32_t hi1 = split2(x1, y1, lo1);
                *(uint32_t*)&Ch[o0] = hi0;  *(uint32_t*)&Cl[o0] = lo0;
                *(uint32_t*)&Ch[o1] = hi1;  *(uint32_t*)&Cl[o1] = lo1;
            } else {
                int nc = n & 1023;
                size_t o0 = (size_t)m * DD + nc;
                size_t o1 = (size_t)(m + 8) * DD + nc;
                if (seg == 0) {
                    uint32_t lo0, lo1;
                    uint32_t hi0 = split2(x0 * 0.125f, y0 * 0.125f, lo0);
                    uint32_t hi1 = split2(x1 * 0.125f, y1 * 0.125f, lo1);
                    *(uint32_t*)&g_qh[o0] = hi0;  *(uint32_t*)&g_ql[o0] = lo0;
                    *(uint32_t*)&g_qh[o1] = hi1;  *(uint32_t*)&g_ql[o1] = lo1;
                } else if (seg == 1) {
                    *(uint32_t*)&g_kh[o0] = pk2(__float2half_rn(x0), __float2half_rn(y0));
                    *(uint32_t*)&g_kh[o1] = pk2(__float2half_rn(x1), __float2half_rn(y1));
                } else {
                    *(uint32_t*)&g_vh[o0] = pk2(__float2half_rn(x0), __float2half_rn(y0));
                    *(uint32_t*)&g_vh[o1] = pk2(__float2half_rn(x1), __float2half_rn(y1));
                }
            }
        }
    }
}

// ============================ flash attention (fp16 mma, fused) — R10 proven shape ============================
#define FA_STR   72
#define FA_ROWB  144
#define FA_TILE  (128 * FA_ROWB)
#define FA_SMEM  (6 * FA_TILE)

__global__ void __launch_bounds__(256, 1) flash_kernel(
    const __half* __restrict__ Qh, const __half* __restrict__ Ql,
    const __half* __restrict__ Kh, const __half* __restrict__ Vh,
    __half* __restrict__ Oh, __half* __restrict__ Ol)
{
    extern __shared__ char smem[];
    uint32_t sb = smem_u32(smem);
    const int bh = blockIdx.x;
    const int qt = 7 - blockIdx.y;
    const int b = bh >> 4, h = bh & 15;
    const int tid = threadIdx.x, wid = tid >> 5, lane = tid & 31;
    const int g = lane >> 2, t4 = lane & 3;
    const int wq = wid * 16 + g;

    const uint32_t sQh = sb, sQl = sb + FA_TILE;
    const uint32_t sKV = sb + 2 * FA_TILE;
    const size_t colbase = (size_t)h * 64;

    {
        int qrow0 = b * LL + qt * 128;
        int krow0 = b * LL;
        #pragma unroll
        for (int i = 0; i < 4; i++) {
            int ch = tid + i * 256;
            int row = ch >> 3, cc = ch & 7;
            uint32_t so = row * FA_ROWB + cc * 16;
            size_t qo = (size_t)(qrow0 + row) * DD + colbase + cc * 8;
            size_t ko = (size_t)(krow0 + row) * DD + colbase + cc * 8;
            cp16(sQh + so, Qh + qo);
            cp16(sQl + so, Ql + qo);
            cp16(sKV + so, Kh + ko);
            cp16(sKV + FA_TILE + so, Vh + ko);
        }
        cp_commit();
    }
    cp_wait0();
    __syncthreads();

    uint32_t qhf[4][4], qlf[4][4];
    {
        uint32_t arow = (uint32_t)(wid * 16 + (lane & 15)) * FA_ROWB;
        #pragma unroll
        for (int kk = 0; kk < 4; kk++) {
            uint32_t aoff = arow + (kk * 16 + (lane >> 4) * 8) * 2;
            ldx4(qhf[kk][0], qhf[kk][1], qhf[kk][2], qhf[kk][3], sQh + aoff);
            ldx4(qlf[kk][0], qlf[kk][1], qlf[kk][2], qlf[kk][3], sQl + aoff);
        }
    }

    float oacc[8][4];
    #pragma unroll
    for (int i = 0; i < 8; i++)
        #pragma unroll
        for (int j = 0; j < 4; j++) oacc[i][j] = 0.f;
    float m0 = -1e30f, m1 = -1e30f, l0 = 0.f, l1 = 0.f;

    for (int kt = 0; kt <= qt; kt++) {
        int buf = kt & 1;
        __syncthreads();
        if (kt < qt) {
            int krow0 = b * LL + (kt + 1) * 128;
            uint32_t dstK = sKV + (buf ^ 1) * 2 * FA_TILE;
            #pragma unroll
            for (int i = 0; i < 4; i++) {
                int ch = tid + i * 256;
                int row = ch >> 3, cc = ch & 7;
                uint32_t so = row * FA_ROWB + cc * 16;
                size_t ko = (size_t)(krow0 + row) * DD + colbase + cc * 8;
                cp16(dstK + so, Kh + ko);
                cp16(dstK + FA_TILE + so, Vh + ko);
            }
            cp_commit();
            cp_wait1();
        } else {
            cp_wait0();
        }
        __syncthreads();

        uint32_t kb = sKV + buf * 2 * FA_TILE;
        uint32_t vb = kb + FA_TILE;

        float s[16][4];
        #pragma unroll
        for (int i = 0; i < 16; i++)
            #pragma unroll
            for (int j = 0; j < 4; j++) s[i][j] = 0.f;

        #pragma unroll
        for (int kk = 0; kk < 4; kk++) {
            #pragma unroll
            for (int nj = 0; nj < 8; nj++) {
                uint32_t boff = kb + (uint32_t)(nj * 16 + (lane >> 4) * 8 + (lane & 7)) * FA_ROWB
                              + (kk * 16 + ((lane >> 3) & 1) * 8) * 2;
                uint32_t b0, b1, b2, b3;
                ldx4(b0, b1, b2, b3, boff);
                mma_fp16(s[2 * nj],     qhf[kk], b0, b1);
                mma_fp16(s[2 * nj],     qlf[kk], b0, b1);
                mma_fp16(s[2 * nj + 1], qhf[kk], b2, b3);
                mma_fp16(s[2 * nj + 1], qlf[kk], b2, b3);
            }
        }

        if (kt == qt) {
            #pragma unroll
            for (int ni = 0; ni < 16; ni++) {
                int cl = ni * 8 + t4 * 2;
                if (cl     > wq)     s[ni][0] = -1e30f;
                if (cl + 1 > wq)     s[ni][1] = -1e30f;
                if (cl     > wq + 8) s[ni][2] = -1e30f;
                if (cl + 1 > wq + 8) s[ni][3] = -1e30f;
            }
        }

        float mx0 = -1e30f, mx1 = -1e30f;
        #pragma unroll
        for (int ni = 0; ni < 16; ni++) {
            mx0 = fmaxf(mx0, fmaxf(s[ni][0], s[ni][1]));
            mx1 = fmaxf(mx1, fmaxf(s[ni][2], s[ni][3]));
        }
        mx0 = fmaxf(mx0, __shfl_xor_sync(0xffffffffu, mx0, 1));
        mx0 = fmaxf(mx0, __shfl_xor_sync(0xffffffffu, mx0, 2));
        mx1 = fmaxf(mx1, __shfl_xor_sync(0xffffffffu, mx1, 1));
        mx1 = fmaxf(mx1, __shfl_xor_sync(0xffffffffu, mx1, 2));
        float nm0 = fmaxf(m0, mx0), nm1 = fmaxf(m1, mx1);
        float f0 = __expf(m0 - nm0), f1 = __expf(m1 - nm1);

        float sum0 = 0.f, sum1 = 0.f;
        #pragma unroll
        for (int ni = 0; ni < 16; ni++) {
            s[ni][0] = __expf(s[ni][0] - nm0);
            s[ni][1] = __expf(s[ni][1] - nm0);
            s[ni][2] = __expf(s[ni][2] - nm1);
            s[ni][3] = __expf(s[ni][3] - nm1);
            sum0 += s[ni][0] + s[ni][1];
            sum1 += s[ni][2] + s[ni][3];
        }
        sum0 += __shfl_xor_sync(0xffffffffu, sum0, 1);
        sum0 += __shfl_xor_sync(0xffffffffu, sum0, 2);
        sum1 += __shfl_xor_sync(0xffffffffu, sum1, 1);
        sum1 += __shfl_xor_sync(0xffffffffu, sum1, 2);
        l0 = l0 * f0 + sum0;
        l1 = l1 * f1 + sum1;
        m0 = nm0; m1 = nm1;

        #pragma unroll
        for (int dj = 0; dj < 8; dj++) {
            oacc[dj][0] *= f0; oacc[dj][1] *= f0;
            oacc[dj][2] *= f1; oacc[dj][3] *= f1;
        }

        #pragma unroll
        for (int kk = 0; kk < 8; kk++) {
            uint32_t ah[4], al[4];
            ah[0] = split2(s[2 * kk][0],     s[2 * kk][1],     al[0]);
            ah[1] = split2(s[2 * kk][2],     s[2 * kk][3],     al[1]);
            ah[2] = split2(s[2 * kk + 1][0], s[2 * kk + 1][1], al[2]);
            ah[3] = split2(s[2 * kk + 1][2], s[2 * kk + 1][3], al[3]);

            uint32_t vrow = (uint32_t)(kk * 16 + (lane & 7) + 8 * ((lane >> 3) & 1)) * FA_ROWB;
            #pragma unroll
            for (int dj = 0; dj < 4; dj++) {
                uint32_t r0, r1, r2, r3;
                ldx4t(r0, r1, r2, r3, vb + vrow + (dj * 16 + (lane >> 4) * 8) * 2);
                mma_fp16(oacc[2 * dj],     ah, r0, r1);
                mma_fp16(oacc[2 * dj],     al, r0, r1);
                mma_fp16(oacc[2 * dj + 1], ah, r2, r3);
                mma_fp16(oacc[2 * dj + 1], al, r2, r3);
            }
        }
    }

    float i0 = 1.f / l0, i1 = 1.f / l1;
    int q0 = qt * 128 + wq;
    size_t r0o = (size_t)(b * LL + q0) * DD + colbase + t4 * 2;
    size_t r1o = r0o + (size_t)8 * DD;
    #pragma unroll
    for (int dj = 0; dj < 8; dj++) {
        uint32_t lo0, lo1;
        uint32_t hi0 = split2(oacc[dj][0] * i0, oacc[dj][1] * i0, lo0);
        uint32_t hi1 = split2(oacc[dj][2] * i1, oacc[dj][3] * i1, lo1);
        *(uint32_t*)&Oh[r0o + dj * 8] = hi0;  *(uint32_t*)&Ol[r0o + dj * 8] = lo0;
        *(uint32_t*)&Oh[r1o + dj * 8] = hi1;  *(uint32_t*)&Ol[r1o + dj * 8] = lo1;
    }
}

// ============================ convAll ============================
__global__ void __launch_bounds__(256) convAll_kernel(
    const float* __restrict__ qkvW, const float* __restrict__ outW,
    const float* __restrict__ w1,   const float* __restrict__ w2)
{
    int bid = blockIdx.x;
    int layer = bid / TILES_PER_LAYER;
    int r = bid % TILES_PER_LAYER;
    const float* src;
    __half* dst;
    int K, N;
    if (r < 3072) {
        src = qkvW + (size_t)layer * DD * D3;
        dst = g_wall + (size_t)layer * LSTRIDE + OFF_QKV;
        K = DD; N = D3;
    } else if (r < 4096) {
        r -= 3072;
        src = outW + (size_t)layer * DD * DD;
        dst = g_wall + (size_t)layer * LSTRIDE + OFF_OUT;
        K = DD; N = DD;
    } else if (r < 8192) {
        r -= 4096;
        src = w1 + (size_t)layer * DD * FF;
        dst = g_wall + (size_t)layer * LSTRIDE + OFF_FFN1;
        K = DD; N = FF;
    } else {
        r -= 8192;
        src = w2 + (size_t)layer * FF * DD;
        dst = g_wall + (size_t)layer * LSTRIDE + OFF_FFN2;
        K = FF; N = DD;
    }
    int ntx = N / 32;
    int nb = (r % ntx) * 32;
    int kb = (r / ntx) * 32;

    __shared__ float tile[32][33];
    int tid = threadIdx.x;
    int tx = tid & 31, ty = tid >> 5;
    #pragma unroll
    for (int q = 0; q < 4; q++)
        tile[ty + 8 * q][tx] = src[(size_t)(kb + ty + 8 * q) * N + nb + tx];
    __syncthreads();
    #pragma unroll
    for (int q = 0; q < 4; q++) {
        int n = nb + ty + 8 * q;
        int k = kb + tx;
        dst[(size_t)n * K + k] = __float2half_rn(tile[tx][ty + 8 * q]);
    }
}

// ---------------- embedding + input proj + posenc (+ planes) ----------------
__global__ void embed_kernel(const int* __restrict__ card_ids,
                             const int* __restrict__ action_ids,
                             const float* __restrict__ bet,
                             const float* __restrict__ card_tab,
                             const float* __restrict__ action_tab,
                             const float* __restrict__ bet_W,
                             const float* __restrict__ bet_b,
                             const float* __restrict__ in_W,
                             const float* __restrict__ in_b)
{
    int t = blockIdx.x;
    int l = t & (LL - 1);
    __shared__ float tok[48];
    int tid = threadIdx.x;
    if (tid < 16)       tok[tid] = card_tab[card_ids[t] * 16 + tid];
    else if (tid < 32)  tok[tid] = action_tab[action_ids[t] * 16 + (tid - 16)];
    else if (tid < 48)  tok[tid] = bet[t] * bet_W[tid - 32] + bet_b[tid - 32];
    __syncthreads();

    const float cdiv = -9.210340371976184f / 1024.0f;
    for (int d = tid; d < DD; d += 256) {
        float acc = in_b[d];
        #pragma unroll
        for (int c = 0; c < 48; c++) acc += tok[c] * in_W[c * DD + d];
        int j2 = d & ~1;
        float ang = (float)l * expf((float)j2 * cdiv);
        float pe = (d & 1) ? cosf(ang) : sinf(ang);
        float x = acc + pe;
        g_x[t * DD + d] = x;
        __half h = __float2half_rn(x);
        g_xh[(size_t)t * DD + d] = h;
        g_xl[(size_t)t * DD + d] = __float2half_rn(x - __half2float(h));
    }
}

// ---------------- residual add + layernorm (+ optional planes) ----------------
__global__ void __launch_bounds__(256) ln_kernel(const float* __restrict__ xin,
                                                 const float* __restrict__ delta,
                                                 const float* __restrict__ gamma,
                                                 const float* __restrict__ beta,
                                                 float* __restrict__ out,
                                                 __half* __restrict__ Ch,
                                                 __half* __restrict__ Cl)
{
    int row = blockIdx.x, tid = threadIdx.x, lane = tid & 31, warp = tid >> 5;
    __shared__ float red1[8];
    __shared__ float red2[8];
    __shared__ float stats[2];

    float v[4];
    float s = 0.f, s2 = 0.f;
    #pragma unroll
    for (int r = 0; r < 4; r++) {
        int d = tid + r * 256;
        float x = xin[(size_t)row * DD + d] + delta[(size_t)row * DD + d];
        v[r] = x; s += x; s2 += x * x;
    }
    #pragma unroll
    for (int o = 16; o > 0; o >>= 1) {
        s  += __shfl_xor_sync(0xffffffffu, s, o);
        s2 += __shfl_xor_sync(0xffffffffu, s2, o);
    }
    if (lane == 0) { red1[warp] = s; red2[warp] = s2; }
    __syncthreads();
    if (tid == 0) {
        float a = 0.f, c = 0.f;
        #pragma unroll
        for (int i = 0; i < 8; i++) { a += red1[i]; c += red2[i]; }
        float mu = a * (1.0f / DD);
        float var = c * (1.0f / DD) - mu * mu;
        stats[0] = mu;
        stats[1] = rsqrtf(var + 1e-5f);
    }
    __syncthreads();
    float mu = stats[0], rstd = stats[1];
    #pragma unroll
    for (int r = 0; r < 4; r++) {
        int d = tid + r * 256;
        float y = (v[r] - mu) * rstd * gamma[d] + beta[d];
        out[(size_t)row * DD + d] = y;
        if (Ch) {
            __half h = __float2half_rn(y);
            Ch[(size_t)row * DD + d] = h;
            Cl[(size_t)row * DD + d] = __float2half_rn(y - __half2float(h));
        }
    }
}

// ---------------- extract x[:, -1] ----------------
__global__ void final_kernel(float* __restrict__ out)
{
    int b = blockIdx.x;
    int d = blockIdx.y * 256 + threadIdx.x;
    out[b * DD + d] = g_x[(size_t)(b * LL + (LL - 1)) * DD + d];
}

// ---------------- host launch ----------------
extern "C" void kernel_launch(void* const* d_in, const int* in_sizes, int n_in,
                              void* d_out, int out_size)
{
    const int*   card_ids   = (const int*)  d_in[0];
    const int*   action_ids = (const int*)  d_in[1];
    const float* bet        = (const float*)d_in[2];
    const float* card_tab   = (const float*)d_in[3];
    const float* action_tab = (const float*)d_in[4];
    const float* bet_W      = (const float*)d_in[5];
    const float* bet_b      = (const float*)d_in[6];
    const float* in_W       = (const float*)d_in[7];
    const float* in_b       = (const float*)d_in[8];
    const float* qkv_W      = (const float*)d_in[9];
    const float* qkv_b      = (const float*)d_in[10];
    const float* out_W      = (const float*)d_in[11];
    const float* out_b      = (const float*)d_in[12];
    const float* ln1_g      = (const float*)d_in[13];
    const float* ln1_b      = (const float*)d_in[14];
    const float* ffn_W1     = (const float*)d_in[15];
    const float* ffn_b1     = (const float*)d_in[16];
    const float* ffn_W2     = (const float*)d_in[17];
    const float* ffn_b2     = (const float*)d_in[18];
    const float* ln2_g      = (const float*)d_in[19];
    const float* ln2_b      = (const float*)d_in[20];

    float *px, *py;
    __half *pxh, *pxl, *poh, *pol, *phh, *phl, *pqh, *pql, *pkh, *pvh, *pwall;
    cudaGetSymbolAddress((void**)&px,    g_x);
    cudaGetSymbolAddress((void**)&py,    g_y);
    cudaGetSymbolAddress((void**)&pxh,   g_xh);
    cudaGetSymbolAddress((void**)&pxl,   g_xl);
    cudaGetSymbolAddress((void**)&poh,   g_oh);
    cudaGetSymbolAddress((void**)&pol,   g_ol);
    cudaGetSymbolAddress((void**)&phh,   g_hh);
    cudaGetSymbolAddress((void**)&phl,   g_hl);
    cudaGetSymbolAddress((void**)&pqh,   g_qh);
    cudaGetSymbolAddress((void**)&pql,   g_ql);
    cudaGetSymbolAddress((void**)&pkh,   g_kh);
    cudaGetSymbolAddress((void**)&pvh,   g_vh);
    cudaGetSymbolAddress((void**)&pwall, g_wall);

    static int configured = 0;
    if (!configured) {
        cudaFuncSetAttribute(tgemm_kernel, cudaFuncAttributeMaxDynamicSharedMemorySize, SMEM_REQ);
        cudaFuncSetAttribute(flash_kernel, cudaFuncAttributeMaxDynamicSharedMemorySize, FA_SMEM);
        configured = 1;
    }

    convAll_kernel<<<NLAYER * TILES_PER_LAYER, 256>>>(qkv_W, out_W, ffn_W1, ffn_W2);

    embed_kernel<<<TT, 256>>>(card_ids, action_ids, bet, card_tab, action_tab,
                              bet_W, bet_b, in_W, in_b);

    for (int i = 0; i < NLAYER; i++) {
        __half* wqkv = pwall + (size_t)i * LSTRIDE + OFF_QKV;
        __half* wout = pwall + (size_t)i * LSTRIDE + OFF_OUT;
        __half* wff1 = pwall + (size_t)i * LSTRIDE + OFF_FFN1;
        __half* wff2 = pwall + (size_t)i * LSTRIDE + OFF_FFN2;
        const float* qkvb_i = qkv_b  + (size_t)i * D3;
        const float* outb_i = out_b  + (size_t)i * DD;
        const float* l1g_i  = ln1_g  + (size_t)i * DD;
        const float* l1b_i  = ln1_b  + (size_t)i * DD;
        const float* b1_i   = ffn_b1 + (size_t)i * FF;
        const float* b2_i   = ffn_b2 + (size_t)i * DD;
        const float* l2g_i  = ln2_g  + (size_t)i * DD;
        const float* l2b_i  = ln2_b  + (size_t)i * DD;

        // qkv projection -> Q/K/V planes (mode 2)
        tgemm_kernel<<<dim3(D3 / 128, TT / 128), 256, SMEM_REQ>>>(
            pxh, pxl, wqkv, qkvb_i, nullptr, nullptr, nullptr, TT, D3, DD, 0, 2);

        // fused flash attention -> O planes
        flash_kernel<<<dim3(32, 8), 256, FA_SMEM>>>(pqh, pql, pkh, pvh, poh, pol);

        // attn out projection -> fp32 delta (mode 0)
        tgemm_kernel<<<dim3(DD / 128, TT / 128), 256, SMEM_REQ>>>(
            poh, pol, wout, outb_i, py, nullptr, nullptr, TT, DD, DD, 0, 0);

        // x = LN(x + attn)
        ln_kernel<<<TT, 256>>>(px, py, l1g_i, l1b_i, px, pxh, pxl);

        // ffn1 (relu) -> hidden planes (mode 1)
        tgemm_kernel<<<dim3(FF / 128, TT / 128), 256, SMEM_REQ>>>(
            pxh, pxl, wff1, b1_i, nullptr, phh, phl, TT, FF, DD, 1, 1);

        // ffn2 -> fp32 delta (mode 0)
        tgemm_kernel<<<dim3(DD / 128, TT / 128), 256, SMEM_REQ>>>(
            phh, phl, wff2, b2_i, py, nullptr, nullptr, TT, DD, FF, 0, 0);

        // x = LN(x + ffn); last layer: skip dead plane writes
        if (i < NLAYER - 1)
            ln_kernel<<<TT, 256>>>(px, py, l2g_i, l2b_i, px, pxh, pxl);
        else
            ln_kernel<<<TT, 256>>>(px, py, l2g_i, l2b_i, px, nullptr, nullptr);
    }

    final_kernel<<<dim3(BB, DD / 256), 256>>>((float*)d_out);
}

// round 15
// speedup vs baseline: 1.1972x; 1.1584x over previous
#include <cuda_runtime.h>
#include <cuda_fp16.h>
#include <cstdint>
#include <math.h>

// Problem constants
#define BB  2
#define LL  1024
#define DD  1024
#define NLAYER 8
#define FF  4096
#define TT  2048          // B*L
#define D3  3072          // 3*D

// weight-buffer layout (halfs per layer)
#define OFF_QKV  0
#define OFF_OUT  3145728
#define OFF_FFN1 4194304
#define OFF_FFN2 8388608
#define LSTRIDE  12582912
#define TILES_PER_LAYER 12288   // 3072 + 1024 + 4096 + 4096

// ---------------- scratch (static device globals; no allocation) ----------------
__device__ float g_x   [TT * DD];
__device__ float g_y   [TT * DD];
__device__ __align__(256) __half g_xh[(size_t)TT * DD];
__device__ __align__(256) __half g_xl[(size_t)TT * DD];
__device__ __align__(256) __half g_oh[(size_t)TT * DD];   // attention output (single plane)
__device__ __align__(256) __half g_hh[(size_t)TT * FF];   // ffn hidden (single plane)
__device__ __align__(256) __half g_qh[(size_t)TT * DD];
__device__ __align__(256) __half g_ql[(size_t)TT * DD];
__device__ __align__(256) __half g_kh[(size_t)TT * DD];
__device__ __align__(256) __half g_vh[(size_t)TT * DD];
__device__ __align__(256) __half g_wall[(size_t)NLAYER * LSTRIDE];

// ============================ PTX helpers ============================
__device__ __forceinline__ uint32_t smem_u32(const void* p) {
    uint32_t a;
    asm("{ .reg .u64 t; cvta.to.shared.u64 t, %1; cvt.u32.u64 %0, t; }" : "=r"(a) : "l"(p));
    return a;
}
__device__ __forceinline__ void cp16(uint32_t dst, const void* src) {
    asm volatile("cp.async.cg.shared.global [%0], [%1], 16;" :: "r"(dst), "l"(src));
}
__device__ __forceinline__ void cp_commit() { asm volatile("cp.async.commit_group;" ::: "memory"); }
__device__ __forceinline__ void cp_wait0()  { asm volatile("cp.async.wait_group 0;" ::: "memory"); }
__device__ __forceinline__ void cp_wait1()  { asm volatile("cp.async.wait_group 1;" ::: "memory"); }

__device__ __forceinline__ void ldx4(uint32_t& r0, uint32_t& r1, uint32_t& r2, uint32_t& r3, uint32_t addr) {
    asm volatile("ldmatrix.sync.aligned.m8n8.x4.shared.b16 {%0,%1,%2,%3}, [%4];"
                 : "=r"(r0), "=r"(r1), "=r"(r2), "=r"(r3) : "r"(addr));
}
__device__ __forceinline__ void ldx4t(uint32_t& r0, uint32_t& r1, uint32_t& r2, uint32_t& r3, uint32_t addr) {
    asm volatile("ldmatrix.sync.aligned.m8n8.x4.trans.shared.b16 {%0,%1,%2,%3}, [%4];"
                 : "=r"(r0), "=r"(r1), "=r"(r2), "=r"(r3) : "r"(addr));
}
__device__ __forceinline__ void mma_fp16(float* c, const uint32_t* a, uint32_t b0, uint32_t b1) {
    asm volatile("mma.sync.aligned.m16n8k16.row.col.f32.f16.f16.f32 "
                 "{%0,%1,%2,%3}, {%4,%5,%6,%7}, {%8,%9}, {%0,%1,%2,%3};"
                 : "+f"(c[0]), "+f"(c[1]), "+f"(c[2]), "+f"(c[3])
                 : "r"(a[0]), "r"(a[1]), "r"(a[2]), "r"(a[3]), "r"(b0), "r"(b1));
}
__device__ __forceinline__ uint32_t pk2(__half x, __half y) {
    __half2 h = __halves2half2(x, y);
    return *(uint32_t*)&h;
}
__device__ __forceinline__ uint32_t split2(float x, float y, uint32_t& lo) {
    __half hx = __float2half_rn(x), hy = __float2half_rn(y);
    lo = pk2(__float2half_rn(x - __half2float(hx)), __float2half_rn(y - __half2float(hy)));
    return pk2(hx, hy);
}

// ============================ tensor GEMM (fp16 2-term, 8 warps x 32x64, 3-stage) ============================
// mode 1: Ch fp16 single plane, with relu (hidden)
// mode 2: qkv split -> g_qh/g_ql (x0.125), g_kh, g_vh (segment by colBase)
#define MP_STR   40
#define MP_ROWB  (MP_STR * 2)
#define MP_TILE  (128 * MP_ROWB)
#define MP_BUF   (3 * MP_TILE)
#define SMEM_REQ (3 * MP_BUF)

__global__ void __launch_bounds__(256, 2) tgemm_kernel(
    const __half* __restrict__ Ah,
    const __half* __restrict__ Al,
    const __half* __restrict__ Bh,
    const float* __restrict__ bias,
    __half* __restrict__ Ch,
    int M, int N, int K, int relu, int mode)
{
    extern __shared__ char smem[];
    uint32_t sb = smem_u32(smem);
    int tid = threadIdx.x;
    int wid = tid >> 5, lane = tid & 31;
    int wm = (wid & 3) * 32;
    int wn = (wid >> 2) * 64;
    const int rowBase = blockIdx.y * 128;
    const int colBase = blockIdx.x * 128;
    const int nkb = K / 32;

    float acc[2][8][4];
    #pragma unroll
    for (int i = 0; i < 2; i++)
        #pragma unroll
        for (int j = 0; j < 8; j++)
            #pragma unroll
            for (int r = 0; r < 4; r++) acc[i][j][r] = 0.f;

    const int lrow = tid >> 1;
    const int lc = (tid & 1) * 16;

    auto loadTile = [&](int kb, int st) {
        uint32_t db = sb + st * MP_BUF;
        uint32_t doff = lrow * MP_ROWB + lc * 2;
        const __half* pAh = Ah + (size_t)(rowBase + lrow) * K + kb * 32 + lc;
        const __half* pAl = Al + (size_t)(rowBase + lrow) * K + kb * 32 + lc;
        const __half* pBh = Bh + (size_t)(colBase + lrow) * K + kb * 32 + lc;
        cp16(db + 0 * MP_TILE + doff,      pAh);     cp16(db + 0 * MP_TILE + doff + 16, pAh + 8);
        cp16(db + 1 * MP_TILE + doff,      pAl);     cp16(db + 1 * MP_TILE + doff + 16, pAl + 8);
        cp16(db + 2 * MP_TILE + doff,      pBh);     cp16(db + 2 * MP_TILE + doff + 16, pBh + 8);
    };

    loadTile(0, 0);
    cp_commit();
    loadTile(1, 1);
    cp_commit();

    int st = 0, ld = 2;
    for (int kb = 0; kb < nkb; kb++) {
        if (kb + 1 < nkb) cp_wait1(); else cp_wait0();
        __syncthreads();
        if (kb + 2 < nkb) { loadTile(kb + 2, ld); cp_commit(); }

        uint32_t ab = sb + st * MP_BUF;
        uint32_t lb = ab + MP_TILE;
        uint32_t hb = ab + 2 * MP_TILE;

        #pragma unroll
        for (int kk = 0; kk < 2; kk++) {
            int k0 = kk * 16;
            uint32_t aoff = (uint32_t)(wm + (lane & 15)) * MP_ROWB + (k0 + (lane >> 4) * 8) * 2;
            uint32_t ah[2][4], al[2][4];
            #pragma unroll
            for (int mi = 0; mi < 2; mi++) {
                ldx4(ah[mi][0], ah[mi][1], ah[mi][2], ah[mi][3], ab + aoff + mi * 16 * MP_ROWB);
                ldx4(al[mi][0], al[mi][1], al[mi][2], al[mi][3], lb + aoff + mi * 16 * MP_ROWB);
            }
            uint32_t bh[16];
            uint32_t boff = (uint32_t)(wn + ((lane >> 4) * 8) + (lane & 7)) * MP_ROWB
                          + (k0 + ((lane >> 3) & 1) * 8) * 2;
            #pragma unroll
            for (int j = 0; j < 4; j++)
                ldx4(bh[4 * j], bh[4 * j + 1], bh[4 * j + 2], bh[4 * j + 3],
                     hb + boff + (uint32_t)(j * 16) * MP_ROWB);

            #pragma unroll
            for (int mi = 0; mi < 2; mi++)
                #pragma unroll
                for (int ni = 0; ni < 8; ni++) {
                    mma_fp16(acc[mi][ni], ah[mi], bh[2 * ni], bh[2 * ni + 1]);
                    mma_fp16(acc[mi][ni], al[mi], bh[2 * ni], bh[2 * ni + 1]);
                }
        }
        st = (st == 2) ? 0 : st + 1;
        ld = (ld == 2) ? 0 : ld + 1;
    }

    int g = lane >> 2, t = lane & 3;
    const int seg = colBase >> 10;            // for mode 2
    #pragma unroll
    for (int mi = 0; mi < 2; mi++) {
        #pragma unroll
        for (int ni = 0; ni < 8; ni++) {
            int m = rowBase + wm + mi * 16 + g;
            int n = colBase + wn + ni * 8 + 2 * t;
            float b0 = bias[n], b1 = bias[n + 1];
            float x0 = acc[mi][ni][0] + b0, y0 = acc[mi][ni][1] + b1;
            float x1 = acc[mi][ni][2] + b0, y1 = acc[mi][ni][3] + b1;
            if (mode == 1) {
                if (relu) {
                    x0 = fmaxf(x0, 0.f); y0 = fmaxf(y0, 0.f);
                    x1 = fmaxf(x1, 0.f); y1 = fmaxf(y1, 0.f);
                }
                size_t o0 = (size_t)m * N + n;
                size_t o1 = (size_t)(m + 8) * N + n;
                *(uint32_t*)&Ch[o0] = pk2(__float2half_rn(x0), __float2half_rn(y0));
                *(uint32_t*)&Ch[o1] = pk2(__float2half_rn(x1), __float2half_rn(y1));
            } else {
                int nc = n & 1023;
                size_t o0 = (size_t)m * DD + nc;
                size_t o1 = (size_t)(m + 8) * DD + nc;
                if (seg == 0) {
                    uint32_t lo0, lo1;
                    uint32_t hi0 = split2(x0 * 0.125f, y0 * 0.125f, lo0);
                    uint32_t hi1 = split2(x1 * 0.125f, y1 * 0.125f, lo1);
                    *(uint32_t*)&g_qh[o0] = hi0;  *(uint32_t*)&g_ql[o0] = lo0;
                    *(uint32_t*)&g_qh[o1] = hi1;  *(uint32_t*)&g_ql[o1] = lo1;
                } else if (seg == 1) {
                    *(uint32_t*)&g_kh[o0] = pk2(__float2half_rn(x0), __float2half_rn(y0));
                    *(uint32_t*)&g_kh[o1] = pk2(__float2half_rn(x1), __float2half_rn(y1));
                } else {
                    *(uint32_t*)&g_vh[o0] = pk2(__float2half_rn(x0), __float2half_rn(y0));
                    *(uint32_t*)&g_vh[o1] = pk2(__float2half_rn(x1), __float2half_rn(y1));
                }
            }
        }
    }
}

// ============================ tensor GEMM single-A-plane (fp32 out) ============================
// For out-proj and ffn2: A single fp16 plane. Same 32x64 warp tile, half the MMAs.
#define S1_BUF   (2 * MP_TILE)      // Ah, Bh = 20480
#define SMEM1    (3 * S1_BUF)       // 61440

__global__ void __launch_bounds__(256, 2) tgemm1_kernel(
    const __half* __restrict__ Ah,
    const __half* __restrict__ Bh,
    const float* __restrict__ bias,
    float* __restrict__ Cf,
    int M, int N, int K)
{
    extern __shared__ char smem[];
    uint32_t sb = smem_u32(smem);
    int tid = threadIdx.x;
    int wid = tid >> 5, lane = tid & 31;
    int wm = (wid & 3) * 32;
    int wn = (wid >> 2) * 64;
    const int rowBase = blockIdx.y * 128;
    const int colBase = blockIdx.x * 128;
    const int nkb = K / 32;

    float acc[2][8][4];
    #pragma unroll
    for (int i = 0; i < 2; i++)
        #pragma unroll
        for (int j = 0; j < 8; j++)
            #pragma unroll
            for (int r = 0; r < 4; r++) acc[i][j][r] = 0.f;

    const int lrow = tid >> 1;
    const int lc = (tid & 1) * 16;

    auto loadTile = [&](int kb, int st) {
        uint32_t db = sb + st * S1_BUF;
        uint32_t doff = lrow * MP_ROWB + lc * 2;
        const __half* pAh = Ah + (size_t)(rowBase + lrow) * K + kb * 32 + lc;
        const __half* pBh = Bh + (size_t)(colBase + lrow) * K + kb * 32 + lc;
        cp16(db + doff,           pAh);  cp16(db + doff + 16,           pAh + 8);
        cp16(db + MP_TILE + doff, pBh);  cp16(db + MP_TILE + doff + 16, pBh + 8);
    };

    loadTile(0, 0);
    cp_commit();
    loadTile(1, 1);
    cp_commit();

    int st = 0, ld = 2;
    for (int kb = 0; kb < nkb; kb++) {
        if (kb + 1 < nkb) cp_wait1(); else cp_wait0();
        __syncthreads();
        if (kb + 2 < nkb) { loadTile(kb + 2, ld); cp_commit(); }

        uint32_t ab = sb + st * S1_BUF;
        uint32_t hb = ab + MP_TILE;

        #pragma unroll
        for (int kk = 0; kk < 2; kk++) {
            int k0 = kk * 16;
            uint32_t aoff = (uint32_t)(wm + (lane & 15)) * MP_ROWB + (k0 + (lane >> 4) * 8) * 2;
            uint32_t ah[2][4];
            #pragma unroll
            for (int mi = 0; mi < 2; mi++)
                ldx4(ah[mi][0], ah[mi][1], ah[mi][2], ah[mi][3], ab + aoff + mi * 16 * MP_ROWB);

            uint32_t bh[16];
            uint32_t boff = (uint32_t)(wn + ((lane >> 4) * 8) + (lane & 7)) * MP_ROWB
                          + (k0 + ((lane >> 3) & 1) * 8) * 2;
            #pragma unroll
            for (int j = 0; j < 4; j++)
                ldx4(bh[4 * j], bh[4 * j + 1], bh[4 * j + 2], bh[4 * j + 3],
                     hb + boff + (uint32_t)(j * 16) * MP_ROWB);

            #pragma unroll
            for (int mi = 0; mi < 2; mi++)
                #pragma unroll
                for (int ni = 0; ni < 8; ni++)
                    mma_fp16(acc[mi][ni], ah[mi], bh[2 * ni], bh[2 * ni + 1]);
        }
        st = (st == 2) ? 0 : st + 1;
        ld = (ld == 2) ? 0 : ld + 1;
    }

    int g = lane >> 2, t = lane & 3;
    #pragma unroll
    for (int mi = 0; mi < 2; mi++) {
        #pragma unroll
        for (int ni = 0; ni < 8; ni++) {
            int m = rowBase + wm + mi * 16 + g;
            int n = colBase + wn + ni * 8 + 2 * t;
            float b0 = bias[n], b1 = bias[n + 1];
            size_t o0 = (size_t)m * N + n;
            size_t o1 = (size_t)(m + 8) * N + n;
            *(float2*)&Cf[o0] = make_float2(acc[mi][ni][0] + b0, acc[mi][ni][1] + b1);
            *(float2*)&Cf[o1] = make_float2(acc[mi][ni][2] + b0, acc[mi][ni][3] + b1);
        }
    }
}

// ============================ flash attention (fp16 mma, fused) — single-plane O out ============================
#define FA_STR   72
#define FA_ROWB  144
#define FA_TILE  (128 * FA_ROWB)
#define FA_SMEM  (6 * FA_TILE)

__global__ void __launch_bounds__(256, 1) flash_kernel(
    const __half* __restrict__ Qh, const __half* __restrict__ Ql,
    const __half* __restrict__ Kh, const __half* __restrict__ Vh,
    __half* __restrict__ Oh)
{
    extern __shared__ char smem[];
    uint32_t sb = smem_u32(smem);
    const int bh = blockIdx.x;
    const int qt = 7 - blockIdx.y;
    const int b = bh >> 4, h = bh & 15;
    const int tid = threadIdx.x, wid = tid >> 5, lane = tid & 31;
    const int g = lane >> 2, t4 = lane & 3;
    const int wq = wid * 16 + g;

    const uint32_t sQh = sb, sQl = sb + FA_TILE;
    const uint32_t sKV = sb + 2 * FA_TILE;
    const size_t colbase = (size_t)h * 64;

    {
        int qrow0 = b * LL + qt * 128;
        int krow0 = b * LL;
        #pragma unroll
        for (int i = 0; i < 4; i++) {
            int ch = tid + i * 256;
            int row = ch >> 3, cc = ch & 7;
            uint32_t so = row * FA_ROWB + cc * 16;
            size_t qo = (size_t)(qrow0 + row) * DD + colbase + cc * 8;
            size_t ko = (size_t)(krow0 + row) * DD + colbase + cc * 8;
            cp16(sQh + so, Qh + qo);
            cp16(sQl + so, Ql + qo);
            cp16(sKV + so, Kh + ko);
            cp16(sKV + FA_TILE + so, Vh + ko);
        }
        cp_commit();
    }
    cp_wait0();
    __syncthreads();

    uint32_t qhf[4][4], qlf[4][4];
    {
        uint32_t arow = (uint32_t)(wid * 16 + (lane & 15)) * FA_ROWB;
        #pragma unroll
        for (int kk = 0; kk < 4; kk++) {
            uint32_t aoff = arow + (kk * 16 + (lane >> 4) * 8) * 2;
            ldx4(qhf[kk][0], qhf[kk][1], qhf[kk][2], qhf[kk][3], sQh + aoff);
            ldx4(qlf[kk][0], qlf[kk][1], qlf[kk][2], qlf[kk][3], sQl + aoff);
        }
    }

    float oacc[8][4];
    #pragma unroll
    for (int i = 0; i < 8; i++)
        #pragma unroll
        for (int j = 0; j < 4; j++) oacc[i][j] = 0.f;
    float m0 = -1e30f, m1 = -1e30f, l0 = 0.f, l1 = 0.f;

    for (int kt = 0; kt <= qt; kt++) {
        int buf = kt & 1;
        __syncthreads();
        if (kt < qt) {
            int krow0 = b * LL + (kt + 1) * 128;
            uint32_t dstK = sKV + (buf ^ 1) * 2 * FA_TILE;
            #pragma unroll
            for (int i = 0; i < 4; i++) {
                int ch = tid + i * 256;
                int row = ch >> 3, cc = ch & 7;
                uint32_t so = row * FA_ROWB + cc * 16;
                size_t ko = (size_t)(krow0 + row) * DD + colbase + cc * 8;
                cp16(dstK + so, Kh + ko);
                cp16(dstK + FA_TILE + so, Vh + ko);
            }
            cp_commit();
            cp_wait1();
        } else {
            cp_wait0();
        }
        __syncthreads();

        uint32_t kb = sKV + buf * 2 * FA_TILE;
        uint32_t vb = kb + FA_TILE;

        float s[16][4];
        #pragma unroll
        for (int i = 0; i < 16; i++)
            #pragma unroll
            for (int j = 0; j < 4; j++) s[i][j] = 0.f;

        #pragma unroll
        for (int kk = 0; kk < 4; kk++) {
            #pragma unroll
            for (int nj = 0; nj < 8; nj++) {
                uint32_t boff = kb + (uint32_t)(nj * 16 + (lane >> 4) * 8 + (lane & 7)) * FA_ROWB
                              + (kk * 16 + ((lane >> 3) & 1) * 8) * 2;
                uint32_t b0, b1, b2, b3;
                ldx4(b0, b1, b2, b3, boff);
                mma_fp16(s[2 * nj],     qhf[kk], b0, b1);
                mma_fp16(s[2 * nj],     qlf[kk], b0, b1);
                mma_fp16(s[2 * nj + 1], qhf[kk], b2, b3);
                mma_fp16(s[2 * nj + 1], qlf[kk], b2, b3);
            }
        }

        if (kt == qt) {
            #pragma unroll
            for (int ni = 0; ni < 16; ni++) {
                int cl = ni * 8 + t4 * 2;
                if (cl     > wq)     s[ni][0] = -1e30f;
                if (cl + 1 > wq)     s[ni][1] = -1e30f;
                if (cl     > wq + 8) s[ni][2] = -1e30f;
                if (cl + 1 > wq + 8) s[ni][3] = -1e30f;
            }
        }

        float mx0 = -1e30f, mx1 = -1e30f;
        #pragma unroll
        for (int ni = 0; ni < 16; ni++) {
            mx0 = fmaxf(mx0, fmaxf(s[ni][0], s[ni][1]));
            mx1 = fmaxf(mx1, fmaxf(s[ni][2], s[ni][3]));
        }
        mx0 = fmaxf(mx0, __shfl_xor_sync(0xffffffffu, mx0, 1));
        mx0 = fmaxf(mx0, __shfl_xor_sync(0xffffffffu, mx0, 2));
        mx1 = fmaxf(mx1, __shfl_xor_sync(0xffffffffu, mx1, 1));
        mx1 = fmaxf(mx1, __shfl_xor_sync(0xffffffffu, mx1, 2));
        float nm0 = fmaxf(m0, mx0), nm1 = fmaxf(m1, mx1);
        float f0 = __expf(m0 - nm0), f1 = __expf(m1 - nm1);

        float sum0 = 0.f, sum1 = 0.f;
        #pragma unroll
        for (int ni = 0; ni < 16; ni++) {
            s[ni][0] = __expf(s[ni][0] - nm0);
            s[ni][1] = __expf(s[ni][1] - nm0);
            s[ni][2] = __expf(s[ni][2] - nm1);
            s[ni][3] = __expf(s[ni][3] - nm1);
            sum0 += s[ni][0] + s[ni][1];
            sum1 += s[ni][2] + s[ni][3];
        }
        sum0 += __shfl_xor_sync(0xffffffffu, sum0, 1);
        sum0 += __shfl_xor_sync(0xffffffffu, sum0, 2);
        sum1 += __shfl_xor_sync(0xffffffffu, sum1, 1);
        sum1 += __shfl_xor_sync(0xffffffffu, sum1, 2);
        l0 = l0 * f0 + sum0;
        l1 = l1 * f1 + sum1;
        m0 = nm0; m1 = nm1;

        #pragma unroll
        for (int dj = 0; dj < 8; dj++) {
            oacc[dj][0] *= f0; oacc[dj][1] *= f0;
            oacc[dj][2] *= f1; oacc[dj][3] *= f1;
        }

        #pragma unroll
        for (int kk = 0; kk < 8; kk++) {
            uint32_t ah[4], al[4];
            ah[0] = split2(s[2 * kk][0],     s[2 * kk][1],     al[0]);
            ah[1] = split2(s[2 * kk][2],     s[2 * kk][3],     al[1]);
            ah[2] = split2(s[2 * kk + 1][0], s[2 * kk + 1][1], al[2]);
            ah[3] = split2(s[2 * kk + 1][2], s[2 * kk + 1][3], al[3]);

            uint32_t vrow = (uint32_t)(kk * 16 + (lane & 7) + 8 * ((lane >> 3) & 1)) * FA_ROWB;
            #pragma unroll
            for (int dj = 0; dj < 4; dj++) {
                uint32_t r0, r1, r2, r3;
                ldx4t(r0, r1, r2, r3, vb + vrow + (dj * 16 + (lane >> 4) * 8) * 2);
                mma_fp16(oacc[2 * dj],     ah, r0, r1);
                mma_fp16(oacc[2 * dj],     al, r0, r1);
                mma_fp16(oacc[2 * dj + 1], ah, r2, r3);
                mma_fp16(oacc[2 * dj + 1], al, r2, r3);
            }
        }
    }

    // epilogue: single fp16 plane (out-proj uses single-plane A now)
    float i0 = 1.f / l0, i1 = 1.f / l1;
    int q0 = qt * 128 + wq;
    size_t r0o = (size_t)(b * LL + q0) * DD + colbase + t4 * 2;
    size_t r1o = r0o + (size_t)8 * DD;
    #pragma unroll
    for (int dj = 0; dj < 8; dj++) {
        *(uint32_t*)&Oh[r0o + dj * 8] = pk2(__float2half_rn(oacc[dj][0] * i0),
                                            __float2half_rn(oacc[dj][1] * i0));
        *(uint32_t*)&Oh[r1o + dj * 8] = pk2(__float2half_rn(oacc[dj][2] * i1),
                                            __float2half_rn(oacc[dj][3] * i1));
    }
}

// ============================ convAll ============================
__global__ void __launch_bounds__(256) convAll_kernel(
    const float* __restrict__ qkvW, const float* __restrict__ outW,
    const float* __restrict__ w1,   const float* __restrict__ w2)
{
    int bid = blockIdx.x;
    int layer = bid / TILES_PER_LAYER;
    int r = bid % TILES_PER_LAYER;
    const float* src;
    __half* dst;
    int K, N;
    if (r < 3072) {
        src = qkvW + (size_t)layer * DD * D3;
        dst = g_wall + (size_t)layer * LSTRIDE + OFF_QKV;
        K = DD; N = D3;
    } else if (r < 4096) {
        r -= 3072;
        src = outW + (size_t)layer * DD * DD;
        dst = g_wall + (size_t)layer * LSTRIDE + OFF_OUT;
        K = DD; N = DD;
    } else if (r < 8192) {
        r -= 4096;
        src = w1 + (size_t)layer * DD * FF;
        dst = g_wall + (size_t)layer * LSTRIDE + OFF_FFN1;
        K = DD; N = FF;
    } else {
        r -= 8192;
        src = w2 + (size_t)layer * FF * DD;
        dst = g_wall + (size_t)layer * LSTRIDE + OFF_FFN2;
        K = FF; N = DD;
    }
    int ntx = N / 32;
    int nb = (r % ntx) * 32;
    int kb = (r / ntx) * 32;

    __shared__ float tile[32][33];
    int tid = threadIdx.x;
    int tx = tid & 31, ty = tid >> 5;
    #pragma unroll
    for (int q = 0; q < 4; q++)
        tile[ty + 8 * q][tx] = src[(size_t)(kb + ty + 8 * q) * N + nb + tx];
    __syncthreads();
    #pragma unroll
    for (int q = 0; q < 4; q++) {
        int n = nb + ty + 8 * q;
        int k = kb + tx;
        dst[(size_t)n * K + k] = __float2half_rn(tile[tx][ty + 8 * q]);
    }
}

// ---------------- embedding + input proj + posenc (+ planes) ----------------
__global__ void embed_kernel(const int* __restrict__ card_ids,
                             const int* __restrict__ action_ids,
                             const float* __restrict__ bet,
                             const float* __restrict__ card_tab,
                             const float* __restrict__ action_tab,
                             const float* __restrict__ bet_W,
                             const float* __restrict__ bet_b,
                             const float* __restrict__ in_W,
                             const float* __restrict__ in_b)
{
    int t = blockIdx.x;
    int l = t & (LL - 1);
    __shared__ float tok[48];
    int tid = threadIdx.x;
    if (tid < 16)       tok[tid] = card_tab[card_ids[t] * 16 + tid];
    else if (tid < 32)  tok[tid] = action_tab[action_ids[t] * 16 + (tid - 16)];
    else if (tid < 48)  tok[tid] = bet[t] * bet_W[tid - 32] + bet_b[tid - 32];
    __syncthreads();

    const float cdiv = -9.210340371976184f / 1024.0f;
    for (int d = tid; d < DD; d += 256) {
        float acc = in_b[d];
        #pragma unroll
        for (int c = 0; c < 48; c++) acc += tok[c] * in_W[c * DD + d];
        int j2 = d & ~1;
        float ang = (float)l * expf((float)j2 * cdiv);
        float pe = (d & 1) ? cosf(ang) : sinf(ang);
        float x = acc + pe;
        g_x[t * DD + d] = x;
        __half h = __float2half_rn(x);
        g_xh[(size_t)t * DD + d] = h;
        g_xl[(size_t)t * DD + d] = __float2half_rn(x - __half2float(h));
    }
}

// ---------------- residual add + layernorm (+ optional planes) ----------------
__global__ void __launch_bounds__(256) ln_kernel(const float* __restrict__ xin,
                                                 const float* __restrict__ delta,
                                                 const float* __restrict__ gamma,
                                                 const float* __restrict__ beta,
                                                 float* __restrict__ out,
                                                 __half* __restrict__ Ch,
                                                 __half* __restrict__ Cl)
{
    int row = blockIdx.x, tid = threadIdx.x, lane = tid & 31, warp = tid >> 5;
    __shared__ float red1[8];
    __shared__ float red2[8];
    __shared__ float stats[2];

    float v[4];
    float s = 0.f, s2 = 0.f;
    #pragma unroll
    for (int r = 0; r < 4; r++) {
        int d = tid + r * 256;
        float x = xin[(size_t)row * DD + d] + delta[(size_t)row * DD + d];
        v[r] = x; s += x; s2 += x * x;
    }
    #pragma unroll
    for (int o = 16; o > 0; o >>= 1) {
        s  += __shfl_xor_sync(0xffffffffu, s, o);
        s2 += __shfl_xor_sync(0xffffffffu, s2, o);
    }
    if (lane == 0) { red1[warp] = s; red2[warp] = s2; }
    __syncthreads();
    if (tid == 0) {
        float a = 0.f, c = 0.f;
        #pragma unroll
        for (int i = 0; i < 8; i++) { a += red1[i]; c += red2[i]; }
        float mu = a * (1.0f / DD);
        float var = c * (1.0f / DD) - mu * mu;
        stats[0] = mu;
        stats[1] = rsqrtf(var + 1e-5f);
    }
    __syncthreads();
    float mu = stats[0], rstd = stats[1];
    #pragma unroll
    for (int r = 0; r < 4; r++) {
        int d = tid + r * 256;
        float y = (v[r] - mu) * rstd * gamma[d] + beta[d];
        out[(size_t)row * DD + d] = y;
        if (Ch) {
            __half h = __float2half_rn(y);
            Ch[(size_t)row * DD + d] = h;
            Cl[(size_t)row * DD + d] = __float2half_rn(y - __half2float(h));
        }
    }
}

// ---------------- extract x[:, -1] ----------------
__global__ void final_kernel(float* __restrict__ out)
{
    int b = blockIdx.x;
    int d = blockIdx.y * 256 + threadIdx.x;
    out[b * DD + d] = g_x[(size_t)(b * LL + (LL - 1)) * DD + d];
}

// ---------------- host launch ----------------
extern "C" void kernel_launch(void* const* d_in, const int* in_sizes, int n_in,
                              void* d_out, int out_size)
{
    const int*   card_ids   = (const int*)  d_in[0];
    const int*   action_ids = (const int*)  d_in[1];
    const float* bet        = (const float*)d_in[2];
    const float* card_tab   = (const float*)d_in[3];
    const float* action_tab = (const float*)d_in[4];
    const float* bet_W      = (const float*)d_in[5];
    const float* bet_b      = (const float*)d_in[6];
    const float* in_W       = (const float*)d_in[7];
    const float* in_b       = (const float*)d_in[8];
    const float* qkv_W      = (const float*)d_in[9];
    const float* qkv_b      = (const float*)d_in[10];
    const float* out_W      = (const float*)d_in[11];
    const float* out_b      = (const float*)d_in[12];
    const float* ln1_g      = (const float*)d_in[13];
    const float* ln1_b      = (const float*)d_in[14];
    const float* ffn_W1     = (const float*)d_in[15];
    const float* ffn_b1     = (const float*)d_in[16];
    const float* ffn_W2     = (const float*)d_in[17];
    const float* ffn_b2     = (const float*)d_in[18];
    const float* ln2_g      = (const float*)d_in[19];
    const float* ln2_b      = (const float*)d_in[20];

    float *px, *py;
    __half *pxh, *pxl, *poh, *phh, *pqh, *pql, *pkh, *pvh, *pwall;
    cudaGetSymbolAddress((void**)&px,    g_x);
    cudaGetSymbolAddress((void**)&py,    g_y);
    cudaGetSymbolAddress((void**)&pxh,   g_xh);
    cudaGetSymbolAddress((void**)&pxl,   g_xl);
    cudaGetSymbolAddress((void**)&poh,   g_oh);
    cudaGetSymbolAddress((void**)&phh,   g_hh);
    cudaGetSymbolAddress((void**)&pqh,   g_qh);
    cudaGetSymbolAddress((void**)&pql,   g_ql);
    cudaGetSymbolAddress((void**)&pkh,   g_kh);
    cudaGetSymbolAddress((void**)&pvh,   g_vh);
    cudaGetSymbolAddress((void**)&pwall, g_wall);

    static int configured = 0;
    if (!configured) {
        cudaFuncSetAttribute(tgemm_kernel,  cudaFuncAttributeMaxDynamicSharedMemorySize, SMEM_REQ);
        cudaFuncSetAttribute(tgemm1_kernel, cudaFuncAttributeMaxDynamicSharedMemorySize, SMEM1);
        cudaFuncSetAttribute(flash_kernel,  cudaFuncAttributeMaxDynamicSharedMemorySize, FA_SMEM);
        configured = 1;
    }

    convAll_kernel<<<NLAYER * TILES_PER_LAYER, 256>>>(qkv_W, out_W, ffn_W1, ffn_W2);

    embed_kernel<<<TT, 256>>>(card_ids, action_ids, bet, card_tab, action_tab,
                              bet_W, bet_b, in_W, in_b);

    for (int i = 0; i < NLAYER; i++) {
        __half* wqkv = pwall + (size_t)i * LSTRIDE + OFF_QKV;
        __half* wout = pwall + (size_t)i * LSTRIDE + OFF_OUT;
        __half* wff1 = pwall + (size_t)i * LSTRIDE + OFF_FFN1;
        __half* wff2 = pwall + (size_t)i * LSTRIDE + OFF_FFN2;
        const float* qkvb_i = qkv_b  + (size_t)i * D3;
        const float* outb_i = out_b  + (size_t)i * DD;
        const float* l1g_i  = ln1_g  + (size_t)i * DD;
        const float* l1b_i  = ln1_b  + (size_t)i * DD;
        const float* b1_i   = ffn_b1 + (size_t)i * FF;
        const float* b2_i   = ffn_b2 + (size_t)i * DD;
        const float* l2g_i  = ln2_g  + (size_t)i * DD;
        const float* l2b_i  = ln2_b  + (size_t)i * DD;

        // qkv projection -> Q/K/V planes (mode 2, full 2-term precision)
        tgemm_kernel<<<dim3(D3 / 128, TT / 128), 256, SMEM_REQ>>>(
            pxh, pxl, wqkv, qkvb_i, nullptr, TT, D3, DD, 0, 2);

        // fused flash attention -> O (single fp16 plane)
        flash_kernel<<<dim3(32, 8), 256, FA_SMEM>>>(pqh, pql, pkh, pvh, poh);

        // attn out projection: single-A-plane GEMM -> fp32 delta
        tgemm1_kernel<<<dim3(DD / 128, TT / 128), 256, SMEM1>>>(
            poh, wout, outb_i, py, TT, DD, DD);

        // x = LN(x + attn)
        ln_kernel<<<TT, 256>>>(px, py, l1g_i, l1b_i, px, pxh, pxl);

        // ffn1 (relu) -> hidden single plane (mode 1, full 2-term input precision)
        tgemm_kernel<<<dim3(FF / 128, TT / 128), 256, SMEM_REQ>>>(
            pxh, pxl, wff1, b1_i, phh, TT, FF, DD, 1, 1);

        // ffn2: single-A-plane GEMM -> fp32 delta
        tgemm1_kernel<<<dim3(DD / 128, TT / 128), 256, SMEM1>>>(
            phh, wff2, b2_i, py, TT, DD, FF);

        // x = LN(x + ffn); last layer: skip dead plane writes
        if (i < NLAYER - 1)
            ln_kernel<<<TT, 256>>>(px, py, l2g_i, l2b_i, px, pxh, pxl);
        else
            ln_kernel<<<TT, 256>>>(px, py, l2g_i, l2b_i, px, nullptr, nullptr);
    }

    final_kernel<<<dim3(BB, DD / 256), 256>>>((float*)d_out);
}

// round 16
// speedup vs baseline: 1.4876x; 1.2425x over previous
#include <cuda_runtime.h>
#include <cuda_fp16.h>
#include <cstdint>
#include <math.h>

// Problem constants
#define BB  2
#define LL  1024
#define DD  1024
#define NLAYER 8
#define FF  4096
#define TT  2048          // B*L
#define D3  3072          // 3*D

// weight-buffer layout (halfs per layer)
#define OFF_QKV  0
#define OFF_OUT  3145728
#define OFF_FFN1 4194304
#define OFF_FFN2 8388608
#define LSTRIDE  12582912
#define TILES_PER_LAYER 12288   // 3072 + 1024 + 4096 + 4096

// ---------------- scratch (static device globals; no allocation) ----------------
__device__ float g_x   [TT * DD];
__device__ float g_y   [TT * DD];
__device__ __align__(256) __half g_xh[(size_t)TT * DD];   // residual stream (single fp16 plane)
__device__ __align__(256) __half g_oh[(size_t)TT * DD];   // attention output (single plane)
__device__ __align__(256) __half g_hh[(size_t)TT * FF];   // ffn hidden (single plane)
__device__ __align__(256) __half g_qh[(size_t)TT * DD];   // Q hi (scaled 1/8, from fp32 acc)
__device__ __align__(256) __half g_ql[(size_t)TT * DD];   // Q lo
__device__ __align__(256) __half g_kh[(size_t)TT * DD];   // K fp16
__device__ __align__(256) __half g_vh[(size_t)TT * DD];   // V fp16
__device__ __align__(256) __half g_wall[(size_t)NLAYER * LSTRIDE];

// ============================ PTX helpers ============================
__device__ __forceinline__ uint32_t smem_u32(const void* p) {
    uint32_t a;
    asm("{ .reg .u64 t; cvta.to.shared.u64 t, %1; cvt.u32.u64 %0, t; }" : "=r"(a) : "l"(p));
    return a;
}
__device__ __forceinline__ void cp16(uint32_t dst, const void* src) {
    asm volatile("cp.async.cg.shared.global [%0], [%1], 16;" :: "r"(dst), "l"(src));
}
__device__ __forceinline__ void cp_commit() { asm volatile("cp.async.commit_group;" ::: "memory"); }
__device__ __forceinline__ void cp_wait0()  { asm volatile("cp.async.wait_group 0;" ::: "memory"); }
__device__ __forceinline__ void cp_wait1()  { asm volatile("cp.async.wait_group 1;" ::: "memory"); }

__device__ __forceinline__ void ldx4(uint32_t& r0, uint32_t& r1, uint32_t& r2, uint32_t& r3, uint32_t addr) {
    asm volatile("ldmatrix.sync.aligned.m8n8.x4.shared.b16 {%0,%1,%2,%3}, [%4];"
                 : "=r"(r0), "=r"(r1), "=r"(r2), "=r"(r3) : "r"(addr));
}
__device__ __forceinline__ void ldx4t(uint32_t& r0, uint32_t& r1, uint32_t& r2, uint32_t& r3, uint32_t addr) {
    asm volatile("ldmatrix.sync.aligned.m8n8.x4.trans.shared.b16 {%0,%1,%2,%3}, [%4];"
                 : "=r"(r0), "=r"(r1), "=r"(r2), "=r"(r3) : "r"(addr));
}
__device__ __forceinline__ void mma_fp16(float* c, const uint32_t* a, uint32_t b0, uint32_t b1) {
    asm volatile("mma.sync.aligned.m16n8k16.row.col.f32.f16.f16.f32 "
                 "{%0,%1,%2,%3}, {%4,%5,%6,%7}, {%8,%9}, {%0,%1,%2,%3};"
                 : "+f"(c[0]), "+f"(c[1]), "+f"(c[2]), "+f"(c[3])
                 : "r"(a[0]), "r"(a[1]), "r"(a[2]), "r"(a[3]), "r"(b0), "r"(b1));
}
__device__ __forceinline__ uint32_t pk2(__half x, __half y) {
    __half2 h = __halves2half2(x, y);
    return *(uint32_t*)&h;
}
__device__ __forceinline__ uint32_t split2(float x, float y, uint32_t& lo) {
    __half hx = __float2half_rn(x), hy = __float2half_rn(y);
    lo = pk2(__float2half_rn(x - __half2float(hx)), __float2half_rn(y - __half2float(hy)));
    return pk2(hx, hy);
}

// ============================ tensor GEMM (single A plane, 8 warps x 32x64, 3-stage) ============================
// mode 0: Cf fp32 = A@B^T + bias
// mode 1: Ch fp16 single plane, with relu
// mode 2: qkv split -> g_qh/g_ql (x0.125, split from fp32 acc), g_kh, g_vh (segment by colBase)
#define MP_STR   40
#define MP_ROWB  (MP_STR * 2)
#define MP_TILE  (128 * MP_ROWB)
#define S1_BUF   (2 * MP_TILE)      // Ah, Bh = 20480
#define SMEM1    (3 * S1_BUF)       // 61440

__global__ void __launch_bounds__(256, 2) tgemm_kernel(
    const __half* __restrict__ Ah,
    const __half* __restrict__ Bh,
    const float* __restrict__ bias,
    float* __restrict__ Cf,
    __half* __restrict__ Ch,
    int M, int N, int K, int relu, int mode)
{
    extern __shared__ char smem[];
    uint32_t sb = smem_u32(smem);
    int tid = threadIdx.x;
    int wid = tid >> 5, lane = tid & 31;
    int wm = (wid & 3) * 32;
    int wn = (wid >> 2) * 64;
    const int rowBase = blockIdx.y * 128;
    const int colBase = blockIdx.x * 128;
    const int nkb = K / 32;

    float acc[2][8][4];
    #pragma unroll
    for (int i = 0; i < 2; i++)
        #pragma unroll
        for (int j = 0; j < 8; j++)
            #pragma unroll
            for (int r = 0; r < 4; r++) acc[i][j][r] = 0.f;

    const int lrow = tid >> 1;
    const int lc = (tid & 1) * 16;

    auto loadTile = [&](int kb, int st) {
        uint32_t db = sb + st * S1_BUF;
        uint32_t doff = lrow * MP_ROWB + lc * 2;
        const __half* pAh = Ah + (size_t)(rowBase + lrow) * K + kb * 32 + lc;
        const __half* pBh = Bh + (size_t)(colBase + lrow) * K + kb * 32 + lc;
        cp16(db + doff,           pAh);  cp16(db + doff + 16,           pAh + 8);
        cp16(db + MP_TILE + doff, pBh);  cp16(db + MP_TILE + doff + 16, pBh + 8);
    };

    loadTile(0, 0);
    cp_commit();
    loadTile(1, 1);
    cp_commit();

    int st = 0, ld = 2;
    for (int kb = 0; kb < nkb; kb++) {
        if (kb + 1 < nkb) cp_wait1(); else cp_wait0();
        __syncthreads();
        if (kb + 2 < nkb) { loadTile(kb + 2, ld); cp_commit(); }

        uint32_t ab = sb + st * S1_BUF;
        uint32_t hb = ab + MP_TILE;

        #pragma unroll
        for (int kk = 0; kk < 2; kk++) {
            int k0 = kk * 16;
            uint32_t aoff = (uint32_t)(wm + (lane & 15)) * MP_ROWB + (k0 + (lane >> 4) * 8) * 2;
            uint32_t ah[2][4];
            #pragma unroll
            for (int mi = 0; mi < 2; mi++)
                ldx4(ah[mi][0], ah[mi][1], ah[mi][2], ah[mi][3], ab + aoff + mi * 16 * MP_ROWB);

            uint32_t bh[16];
            uint32_t boff = (uint32_t)(wn + ((lane >> 4) * 8) + (lane & 7)) * MP_ROWB
                          + (k0 + ((lane >> 3) & 1) * 8) * 2;
            #pragma unroll
            for (int j = 0; j < 4; j++)
                ldx4(bh[4 * j], bh[4 * j + 1], bh[4 * j + 2], bh[4 * j + 3],
                     hb + boff + (uint32_t)(j * 16) * MP_ROWB);

            #pragma unroll
            for (int mi = 0; mi < 2; mi++)
                #pragma unroll
                for (int ni = 0; ni < 8; ni++)
                    mma_fp16(acc[mi][ni], ah[mi], bh[2 * ni], bh[2 * ni + 1]);
        }
        st = (st == 2) ? 0 : st + 1;
        ld = (ld == 2) ? 0 : ld + 1;
    }

    int g = lane >> 2, t = lane & 3;
    const int seg = colBase >> 10;            // for mode 2
    #pragma unroll
    for (int mi = 0; mi < 2; mi++) {
        #pragma unroll
        for (int ni = 0; ni < 8; ni++) {
            int m = rowBase + wm + mi * 16 + g;
            int n = colBase + wn + ni * 8 + 2 * t;
            float b0 = bias[n], b1 = bias[n + 1];
            float x0 = acc[mi][ni][0] + b0, y0 = acc[mi][ni][1] + b1;
            float x1 = acc[mi][ni][2] + b0, y1 = acc[mi][ni][3] + b1;
            if (mode == 0) {
                size_t o0 = (size_t)m * N + n;
                size_t o1 = (size_t)(m + 8) * N + n;
                *(float2*)&Cf[o0] = make_float2(x0, y0);
                *(float2*)&Cf[o1] = make_float2(x1, y1);
            } else if (mode == 1) {
                if (relu) {
                    x0 = fmaxf(x0, 0.f); y0 = fmaxf(y0, 0.f);
                    x1 = fmaxf(x1, 0.f); y1 = fmaxf(y1, 0.f);
                }
                size_t o0 = (size_t)m * N + n;
                size_t o1 = (size_t)(m + 8) * N + n;
                *(uint32_t*)&Ch[o0] = pk2(__float2half_rn(x0), __float2half_rn(y0));
                *(uint32_t*)&Ch[o1] = pk2(__float2half_rn(x1), __float2half_rn(y1));
            } else {
                int nc = n & 1023;
                size_t o0 = (size_t)m * DD + nc;
                size_t o1 = (size_t)(m + 8) * DD + nc;
                if (seg == 0) {
                    uint32_t lo0, lo1;
                    uint32_t hi0 = split2(x0 * 0.125f, y0 * 0.125f, lo0);
                    uint32_t hi1 = split2(x1 * 0.125f, y1 * 0.125f, lo1);
                    *(uint32_t*)&g_qh[o0] = hi0;  *(uint32_t*)&g_ql[o0] = lo0;
                    *(uint32_t*)&g_qh[o1] = hi1;  *(uint32_t*)&g_ql[o1] = lo1;
                } else if (seg == 1) {
                    *(uint32_t*)&g_kh[o0] = pk2(__float2half_rn(x0), __float2half_rn(y0));
                    *(uint32_t*)&g_kh[o1] = pk2(__float2half_rn(x1), __float2half_rn(y1));
                } else {
                    *(uint32_t*)&g_vh[o0] = pk2(__float2half_rn(x0), __float2half_rn(y0));
                    *(uint32_t*)&g_vh[o1] = pk2(__float2half_rn(x1), __float2half_rn(y1));
                }
            }
        }
    }
}

// ============================ flash attention (fp16 mma, fused) — R10 proven shape ============================
#define FA_STR   72
#define FA_ROWB  144
#define FA_TILE  (128 * FA_ROWB)
#define FA_SMEM  (6 * FA_TILE)

__global__ void __launch_bounds__(256, 1) flash_kernel(
    const __half* __restrict__ Qh, const __half* __restrict__ Ql,
    const __half* __restrict__ Kh, const __half* __restrict__ Vh,
    __half* __restrict__ Oh)
{
    extern __shared__ char smem[];
    uint32_t sb = smem_u32(smem);
    const int bh = blockIdx.x;
    const int qt = 7 - blockIdx.y;
    const int b = bh >> 4, h = bh & 15;
    const int tid = threadIdx.x, wid = tid >> 5, lane = tid & 31;
    const int g = lane >> 2, t4 = lane & 3;
    const int wq = wid * 16 + g;

    const uint32_t sQh = sb, sQl = sb + FA_TILE;
    const uint32_t sKV = sb + 2 * FA_TILE;
    const size_t colbase = (size_t)h * 64;

    {
        int qrow0 = b * LL + qt * 128;
        int krow0 = b * LL;
        #pragma unroll
        for (int i = 0; i < 4; i++) {
            int ch = tid + i * 256;
            int row = ch >> 3, cc = ch & 7;
            uint32_t so = row * FA_ROWB + cc * 16;
            size_t qo = (size_t)(qrow0 + row) * DD + colbase + cc * 8;
            size_t ko = (size_t)(krow0 + row) * DD + colbase + cc * 8;
            cp16(sQh + so, Qh + qo);
            cp16(sQl + so, Ql + qo);
            cp16(sKV + so, Kh + ko);
            cp16(sKV + FA_TILE + so, Vh + ko);
        }
        cp_commit();
    }
    cp_wait0();
    __syncthreads();

    uint32_t qhf[4][4], qlf[4][4];
    {
        uint32_t arow = (uint32_t)(wid * 16 + (lane & 15)) * FA_ROWB;
        #pragma unroll
        for (int kk = 0; kk < 4; kk++) {
            uint32_t aoff = arow + (kk * 16 + (lane >> 4) * 8) * 2;
            ldx4(qhf[kk][0], qhf[kk][1], qhf[kk][2], qhf[kk][3], sQh + aoff);
            ldx4(qlf[kk][0], qlf[kk][1], qlf[kk][2], qlf[kk][3], sQl + aoff);
        }
    }

    float oacc[8][4];
    #pragma unroll
    for (int i = 0; i < 8; i++)
        #pragma unroll
        for (int j = 0; j < 4; j++) oacc[i][j] = 0.f;
    float m0 = -1e30f, m1 = -1e30f, l0 = 0.f, l1 = 0.f;

    for (int kt = 0; kt <= qt; kt++) {
        int buf = kt & 1;
        __syncthreads();
        if (kt < qt) {
            int krow0 = b * LL + (kt + 1) * 128;
            uint32_t dstK = sKV + (buf ^ 1) * 2 * FA_TILE;
            #pragma unroll
            for (int i = 0; i < 4; i++) {
                int ch = tid + i * 256;
                int row = ch >> 3, cc = ch & 7;
                uint32_t so = row * FA_ROWB + cc * 16;
                size_t ko = (size_t)(krow0 + row) * DD + colbase + cc * 8;
                cp16(dstK + so, Kh + ko);
                cp16(dstK + FA_TILE + so, Vh + ko);
            }
            cp_commit();
            cp_wait1();
        } else {
            cp_wait0();
        }
        __syncthreads();

        uint32_t kb = sKV + buf * 2 * FA_TILE;
        uint32_t vb = kb + FA_TILE;

        float s[16][4];
        #pragma unroll
        for (int i = 0; i < 16; i++)
            #pragma unroll
            for (int j = 0; j < 4; j++) s[i][j] = 0.f;

        #pragma unroll
        for (int kk = 0; kk < 4; kk++) {
            #pragma unroll
            for (int nj = 0; nj < 8; nj++) {
                uint32_t boff = kb + (uint32_t)(nj * 16 + (lane >> 4) * 8 + (lane & 7)) * FA_ROWB
                              + (kk * 16 + ((lane >> 3) & 1) * 8) * 2;
                uint32_t b0, b1, b2, b3;
                ldx4(b0, b1, b2, b3, boff);
                mma_fp16(s[2 * nj],     qhf[kk], b0, b1);
                mma_fp16(s[2 * nj],     qlf[kk], b0, b1);
                mma_fp16(s[2 * nj + 1], qhf[kk], b2, b3);
                mma_fp16(s[2 * nj + 1], qlf[kk], b2, b3);
            }
        }

        if (kt == qt) {
            #pragma unroll
            for (int ni = 0; ni < 16; ni++) {
                int cl = ni * 8 + t4 * 2;
                if (cl     > wq)     s[ni][0] = -1e30f;
                if (cl + 1 > wq)     s[ni][1] = -1e30f;
                if (cl     > wq + 8) s[ni][2] = -1e30f;
                if (cl + 1 > wq + 8) s[ni][3] = -1e30f;
            }
        }

        float mx0 = -1e30f, mx1 = -1e30f;
        #pragma unroll
        for (int ni = 0; ni < 16; ni++) {
            mx0 = fmaxf(mx0, fmaxf(s[ni][0], s[ni][1]));
            mx1 = fmaxf(mx1, fmaxf(s[ni][2], s[ni][3]));
        }
        mx0 = fmaxf(mx0, __shfl_xor_sync(0xffffffffu, mx0, 1));
        mx0 = fmaxf(mx0, __shfl_xor_sync(0xffffffffu, mx0, 2));
        mx1 = fmaxf(mx1, __shfl_xor_sync(0xffffffffu, mx1, 1));
        mx1 = fmaxf(mx1, __shfl_xor_sync(0xffffffffu, mx1, 2));
        float nm0 = fmaxf(m0, mx0), nm1 = fmaxf(m1, mx1);
        float f0 = __expf(m0 - nm0), f1 = __expf(m1 - nm1);

        float sum0 = 0.f, sum1 = 0.f;
        #pragma unroll
        for (int ni = 0; ni < 16; ni++) {
            s[ni][0] = __expf(s[ni][0] - nm0);
            s[ni][1] = __expf(s[ni][1] - nm0);
            s[ni][2] = __expf(s[ni][2] - nm1);
            s[ni][3] = __expf(s[ni][3] - nm1);
            sum0 += s[ni][0] + s[ni][1];
            sum1 += s[ni][2] + s[ni][3];
        }
        sum0 += __shfl_xor_sync(0xffffffffu, sum0, 1);
        sum0 += __shfl_xor_sync(0xffffffffu, sum0, 2);
        sum1 += __shfl_xor_sync(0xffffffffu, sum1, 1);
        sum1 += __shfl_xor_sync(0xffffffffu, sum1, 2);
        l0 = l0 * f0 + sum0;
        l1 = l1 * f1 + sum1;
        m0 = nm0; m1 = nm1;

        #pragma unroll
        for (int dj = 0; dj < 8; dj++) {
            oacc[dj][0] *= f0; oacc[dj][1] *= f0;
            oacc[dj][2] *= f1; oacc[dj][3] *= f1;
        }

        #pragma unroll
        for (int kk = 0; kk < 8; kk++) {
            uint32_t ah[4], al[4];
            ah[0] = split2(s[2 * kk][0],     s[2 * kk][1],     al[0]);
            ah[1] = split2(s[2 * kk][2],     s[2 * kk][3],     al[1]);
            ah[2] = split2(s[2 * kk + 1][0], s[2 * kk + 1][1], al[2]);
            ah[3] = split2(s[2 * kk + 1][2], s[2 * kk + 1][3], al[3]);

            uint32_t vrow = (uint32_t)(kk * 16 + (lane & 7) + 8 * ((lane >> 3) & 1)) * FA_ROWB;
            #pragma unroll
            for (int dj = 0; dj < 4; dj++) {
                uint32_t r0, r1, r2, r3;
                ldx4t(r0, r1, r2, r3, vb + vrow + (dj * 16 + (lane >> 4) * 8) * 2);
                mma_fp16(oacc[2 * dj],     ah, r0, r1);
                mma_fp16(oacc[2 * dj],     al, r0, r1);
                mma_fp16(oacc[2 * dj + 1], ah, r2, r3);
                mma_fp16(oacc[2 * dj + 1], al, r2, r3);
            }
        }
    }

    float i0 = 1.f / l0, i1 = 1.f / l1;
    int q0 = qt * 128 + wq;
    size_t r0o = (size_t)(b * LL + q0) * DD + colbase + t4 * 2;
    size_t r1o = r0o + (size_t)8 * DD;
    #pragma unroll
    for (int dj = 0; dj < 8; dj++) {
        *(uint32_t*)&Oh[r0o + dj * 8] = pk2(__float2half_rn(oacc[dj][0] * i0),
                                            __float2half_rn(oacc[dj][1] * i0));
        *(uint32_t*)&Oh[r1o + dj * 8] = pk2(__float2half_rn(oacc[dj][2] * i1),
                                            __float2half_rn(oacc[dj][3] * i1));
    }
}

// ============================ convAll ============================
__global__ void __launch_bounds__(256) convAll_kernel(
    const float* __restrict__ qkvW, const float* __restrict__ outW,
    const float* __restrict__ w1,   const float* __restrict__ w2)
{
    int bid = blockIdx.x;
    int layer = bid / TILES_PER_LAYER;
    int r = bid % TILES_PER_LAYER;
    const float* src;
    __half* dst;
    int K, N;
    if (r < 3072) {
        src = qkvW + (size_t)layer * DD * D3;
        dst = g_wall + (size_t)layer * LSTRIDE + OFF_QKV;
        K = DD; N = D3;
    } else if (r < 4096) {
        r -= 3072;
        src = outW + (size_t)layer * DD * DD;
        dst = g_wall + (size_t)layer * LSTRIDE + OFF_OUT;
        K = DD; N = DD;
    } else if (r < 8192) {
        r -= 4096;
        src = w1 + (size_t)layer * DD * FF;
        dst = g_wall + (size_t)layer * LSTRIDE + OFF_FFN1;
        K = DD; N = FF;
    } else {
        r -= 8192;
        src = w2 + (size_t)layer * FF * DD;
        dst = g_wall + (size_t)layer * LSTRIDE + OFF_FFN2;
        K = FF; N = DD;
    }
    int ntx = N / 32;
    int nb = (r % ntx) * 32;
    int kb = (r / ntx) * 32;

    __shared__ float tile[32][33];
    int tid = threadIdx.x;
    int tx = tid & 31, ty = tid >> 5;
    #pragma unroll
    for (int q = 0; q < 4; q++)
        tile[ty + 8 * q][tx] = src[(size_t)(kb + ty + 8 * q) * N + nb + tx];
    __syncthreads();
    #pragma unroll
    for (int q = 0; q < 4; q++) {
        int n = nb + ty + 8 * q;
        int k = kb + tx;
        dst[(size_t)n * K + k] = __float2half_rn(tile[tx][ty + 8 * q]);
    }
}

// ---------------- embedding + input proj + posenc (+ single plane) ----------------
__global__ void embed_kernel(const int* __restrict__ card_ids,
                             const int* __restrict__ action_ids,
                             const float* __restrict__ bet,
                             const float* __restrict__ card_tab,
                             const float* __restrict__ action_tab,
                             const float* __restrict__ bet_W,
                             const float* __restrict__ bet_b,
                             const float* __restrict__ in_W,
                             const float* __restrict__ in_b)
{
    int t = blockIdx.x;
    int l = t & (LL - 1);
    __shared__ float tok[48];
    int tid = threadIdx.x;
    if (tid < 16)       tok[tid] = card_tab[card_ids[t] * 16 + tid];
    else if (tid < 32)  tok[tid] = action_tab[action_ids[t] * 16 + (tid - 16)];
    else if (tid < 48)  tok[tid] = bet[t] * bet_W[tid - 32] + bet_b[tid - 32];
    __syncthreads();

    const float cdiv = -9.210340371976184f / 1024.0f;
    for (int d = tid; d < DD; d += 256) {
        float acc = in_b[d];
        #pragma unroll
        for (int c = 0; c < 48; c++) acc += tok[c] * in_W[c * DD + d];
        int j2 = d & ~1;
        float ang = (float)l * expf((float)j2 * cdiv);
        float pe = (d & 1) ? cosf(ang) : sinf(ang);
        float x = acc + pe;
        g_x[t * DD + d] = x;
        g_xh[(size_t)t * DD + d] = __float2half_rn(x);
    }
}

// ---------------- residual add + layernorm (+ optional single plane) ----------------
__global__ void __launch_bounds__(256) ln_kernel(const float* __restrict__ xin,
                                                 const float* __restrict__ delta,
                                                 const float* __restrict__ gamma,
                                                 const float* __restrict__ beta,
                                                 float* __restrict__ out,
                                                 __half* __restrict__ Ch)
{
    int row = blockIdx.x, tid = threadIdx.x, lane = tid & 31, warp = tid >> 5;
    __shared__ float red1[8];
    __shared__ float red2[8];
    __shared__ float stats[2];

    float v[4];
    float s = 0.f, s2 = 0.f;
    #pragma unroll
    for (int r = 0; r < 4; r++) {
        int d = tid + r * 256;
        float x = xin[(size_t)row * DD + d] + delta[(size_t)row * DD + d];
        v[r] = x; s += x; s2 += x * x;
    }
    #pragma unroll
    for (int o = 16; o > 0; o >>= 1) {
        s  += __shfl_xor_sync(0xffffffffu, s, o);
        s2 += __shfl_xor_sync(0xffffffffu, s2, o);
    }
    if (lane == 0) { red1[warp] = s; red2[warp] = s2; }
    __syncthreads();
    if (tid == 0) {
        float a = 0.f, c = 0.f;
        #pragma unroll
        for (int i = 0; i < 8; i++) { a += red1[i]; c += red2[i]; }
        float mu = a * (1.0f / DD);
        float var = c * (1.0f / DD) - mu * mu;
        stats[0] = mu;
        stats[1] = rsqrtf(var + 1e-5f);
    }
    __syncthreads();
    float mu = stats[0], rstd = stats[1];
    #pragma unroll
    for (int r = 0; r < 4; r++) {
        int d = tid + r * 256;
        float y = (v[r] - mu) * rstd * gamma[d] + beta[d];
        out[(size_t)row * DD + d] = y;
        if (Ch) Ch[(size_t)row * DD + d] = __float2half_rn(y);
    }
}

// ---------------- extract x[:, -1] ----------------
__global__ void final_kernel(float* __restrict__ out)
{
    int b = blockIdx.x;
    int d = blockIdx.y * 256 + threadIdx.x;
    out[b * DD + d] = g_x[(size_t)(b * LL + (LL - 1)) * DD + d];
}

// ---------------- host launch ----------------
extern "C" void kernel_launch(void* const* d_in, const int* in_sizes, int n_in,
                              void* d_out, int out_size)
{
    const int*   card_ids   = (const int*)  d_in[0];
    const int*   action_ids = (const int*)  d_in[1];
    const float* bet        = (const float*)d_in[2];
    const float* card_tab   = (const float*)d_in[3];
    const float* action_tab = (const float*)d_in[4];
    const float* bet_W      = (const float*)d_in[5];
    const float* bet_b      = (const float*)d_in[6];
    const float* in_W       = (const float*)d_in[7];
    const float* in_b       = (const float*)d_in[8];
    const float* qkv_W      = (const float*)d_in[9];
    const float* qkv_b      = (const float*)d_in[10];
    const float* out_W      = (const float*)d_in[11];
    const float* out_b      = (const float*)d_in[12];
    const float* ln1_g      = (const float*)d_in[13];
    const float* ln1_b      = (const float*)d_in[14];
    const float* ffn_W1     = (const float*)d_in[15];
    const float* ffn_b1     = (const float*)d_in[16];
    const float* ffn_W2     = (const float*)d_in[17];
    const float* ffn_b2     = (const float*)d_in[18];
    const float* ln2_g      = (const float*)d_in[19];
    const float* ln2_b      = (const float*)d_in[20];

    float *px, *py;
    __half *pxh, *poh, *phh, *pqh, *pql, *pkh, *pvh, *pwall;
    cudaGetSymbolAddress((void**)&px,    g_x);
    cudaGetSymbolAddress((void**)&py,    g_y);
    cudaGetSymbolAddress((void**)&pxh,   g_xh);
    cudaGetSymbolAddress((void**)&poh,   g_oh);
    cudaGetSymbolAddress((void**)&phh,   g_hh);
    cudaGetSymbolAddress((void**)&pqh,   g_qh);
    cudaGetSymbolAddress((void**)&pql,   g_ql);
    cudaGetSymbolAddress((void**)&pkh,   g_kh);
    cudaGetSymbolAddress((void**)&pvh,   g_vh);
    cudaGetSymbolAddress((void**)&pwall, g_wall);

    static int configured = 0;
    if (!configured) {
        cudaFuncSetAttribute(tgemm_kernel, cudaFuncAttributeMaxDynamicSharedMemorySize, SMEM1);
        cudaFuncSetAttribute(flash_kernel, cudaFuncAttributeMaxDynamicSharedMemorySize, FA_SMEM);
        configured = 1;
    }

    convAll_kernel<<<NLAYER * TILES_PER_LAYER, 256>>>(qkv_W, out_W, ffn_W1, ffn_W2);

    embed_kernel<<<TT, 256>>>(card_ids, action_ids, bet, card_tab, action_tab,
                              bet_W, bet_b, in_W, in_b);

    for (int i = 0; i < NLAYER; i++) {
        __half* wqkv = pwall + (size_t)i * LSTRIDE + OFF_QKV;
        __half* wout = pwall + (size_t)i * LSTRIDE + OFF_OUT;
        __half* wff1 = pwall + (size_t)i * LSTRIDE + OFF_FFN1;
        __half* wff2 = pwall + (size_t)i * LSTRIDE + OFF_FFN2;
        const float* qkvb_i = qkv_b  + (size_t)i * D3;
        const float* outb_i = out_b  + (size_t)i * DD;
        const float* l1g_i  = ln1_g  + (size_t)i * DD;
        const float* l1b_i  = ln1_b  + (size_t)i * DD;
        const float* b1_i   = ffn_b1 + (size_t)i * FF;
        const float* b2_i   = ffn_b2 + (size_t)i * DD;
        const float* l2g_i  = ln2_g  + (size_t)i * DD;
        const float* l2b_i  = ln2_b  + (size_t)i * DD;

        // qkv projection (single A plane) -> Q hi/lo (split from fp32), K, V (mode 2)
        tgemm_kernel<<<dim3(D3 / 128, TT / 128), 256, SMEM1>>>(
            pxh, wqkv, qkvb_i, nullptr, nullptr, TT, D3, DD, 0, 2);

        // fused flash attention -> O (single fp16 plane)
        flash_kernel<<<dim3(32, 8), 256, FA_SMEM>>>(pqh, pql, pkh, pvh, poh);

        // attn out projection (single A plane) -> fp32 delta (mode 0)
        tgemm_kernel<<<dim3(DD / 128, TT / 128), 256, SMEM1>>>(
            poh, wout, outb_i, py, nullptr, TT, DD, DD, 0, 0);

        // x = LN(x + attn)
        ln_kernel<<<TT, 256>>>(px, py, l1g_i, l1b_i, px, pxh);

        // ffn1 (single A plane, relu) -> hidden single plane (mode 1)
        tgemm_kernel<<<dim3(FF / 128, TT / 128), 256, SMEM1>>>(
            pxh, wff1, b1_i, nullptr, phh, TT, FF, DD, 1, 1);

        // ffn2 (single A plane) -> fp32 delta (mode 0)
        tgemm_kernel<<<dim3(DD / 128, TT / 128), 256, SMEM1>>>(
            phh, wff2, b2_i, py, nullptr, TT, DD, FF, 0, 0);

        // x = LN(x + ffn); last layer: skip dead plane writes
        if (i < NLAYER - 1)
            ln_kernel<<<TT, 256>>>(px, py, l2g_i, l2b_i, px, pxh);
        else
            ln_kernel<<<TT, 256>>>(px, py, l2g_i, l2b_i, px, nullptr);
    }

    final_kernel<<<dim3(BB, DD / 256), 256>>>((float*)d_out);
}

// round 17
// speedup vs baseline: 1.5375x; 1.0336x over previous
#include <cuda_runtime.h>
#include <cuda_fp16.h>
#include <cstdint>
#include <math.h>

// Problem constants
#define BB  2
#define LL  1024
#define DD  1024
#define NLAYER 8
#define FF  4096
#define TT  2048          // B*L
#define D3  3072          // 3*D

// weight-buffer layout (halfs per layer)
#define OFF_QKV  0
#define OFF_OUT  3145728
#define OFF_FFN1 4194304
#define OFF_FFN2 8388608
#define LSTRIDE  12582912
#define TILES_PER_LAYER 12288   // 3072 + 1024 + 4096 + 4096

// ---------------- scratch (static device globals; no allocation) ----------------
__device__ float g_x   [TT * DD];
__device__ float g_y   [TT * DD];
__device__ __align__(256) __half g_xh[(size_t)TT * DD];   // residual stream (single fp16 plane)
__device__ __align__(256) __half g_oh[(size_t)TT * DD];   // attention output (single plane)
__device__ __align__(256) __half g_hh[(size_t)TT * FF];   // ffn hidden (single plane)
__device__ __align__(256) __half g_qh[(size_t)TT * DD];   // Q (scaled 1/8, single plane)
__device__ __align__(256) __half g_kh[(size_t)TT * DD];   // K fp16
__device__ __align__(256) __half g_vh[(size_t)TT * DD];   // V fp16
__device__ __align__(256) __half g_wall[(size_t)NLAYER * LSTRIDE];

// ============================ PTX helpers ============================
__device__ __forceinline__ uint32_t smem_u32(const void* p) {
    uint32_t a;
    asm("{ .reg .u64 t; cvta.to.shared.u64 t, %1; cvt.u32.u64 %0, t; }" : "=r"(a) : "l"(p));
    return a;
}
__device__ __forceinline__ void cp16(uint32_t dst, const void* src) {
    asm volatile("cp.async.cg.shared.global [%0], [%1], 16;" :: "r"(dst), "l"(src));
}
__device__ __forceinline__ void cp_commit() { asm volatile("cp.async.commit_group;" ::: "memory"); }
__device__ __forceinline__ void cp_wait0()  { asm volatile("cp.async.wait_group 0;" ::: "memory"); }
__device__ __forceinline__ void cp_wait1()  { asm volatile("cp.async.wait_group 1;" ::: "memory"); }

__device__ __forceinline__ void ldx4(uint32_t& r0, uint32_t& r1, uint32_t& r2, uint32_t& r3, uint32_t addr) {
    asm volatile("ldmatrix.sync.aligned.m8n8.x4.shared.b16 {%0,%1,%2,%3}, [%4];"
                 : "=r"(r0), "=r"(r1), "=r"(r2), "=r"(r3) : "r"(addr));
}
__device__ __forceinline__ void ldx4t(uint32_t& r0, uint32_t& r1, uint32_t& r2, uint32_t& r3, uint32_t addr) {
    asm volatile("ldmatrix.sync.aligned.m8n8.x4.trans.shared.b16 {%0,%1,%2,%3}, [%4];"
                 : "=r"(r0), "=r"(r1), "=r"(r2), "=r"(r3) : "r"(addr));
}
__device__ __forceinline__ void mma_fp16(float* c, const uint32_t* a, uint32_t b0, uint32_t b1) {
    asm volatile("mma.sync.aligned.m16n8k16.row.col.f32.f16.f16.f32 "
                 "{%0,%1,%2,%3}, {%4,%5,%6,%7}, {%8,%9}, {%0,%1,%2,%3};"
                 : "+f"(c[0]), "+f"(c[1]), "+f"(c[2]), "+f"(c[3])
                 : "r"(a[0]), "r"(a[1]), "r"(a[2]), "r"(a[3]), "r"(b0), "r"(b1));
}
__device__ __forceinline__ uint32_t pk2(__half x, __half y) {
    __half2 h = __halves2half2(x, y);
    return *(uint32_t*)&h;
}

// ============================ tensor GEMM (single A plane, 8 warps x 32x64, 3-stage) ============================
// mode 0: Cf fp32 = A@B^T + bias
// mode 1: Ch fp16 single plane, with relu
// mode 2: qkv -> g_qh (x0.125), g_kh, g_vh (segment by colBase), all single fp16
#define MP_STR   40
#define MP_ROWB  (MP_STR * 2)
#define MP_TILE  (128 * MP_ROWB)
#define S1_BUF   (2 * MP_TILE)      // Ah, Bh = 20480
#define SMEM1    (3 * S1_BUF)       // 61440

__global__ void __launch_bounds__(256, 2) tgemm_kernel(
    const __half* __restrict__ Ah,
    const __half* __restrict__ Bh,
    const float* __restrict__ bias,
    float* __restrict__ Cf,
    __half* __restrict__ Ch,
    int M, int N, int K, int relu, int mode)
{
    extern __shared__ char smem[];
    uint32_t sb = smem_u32(smem);
    int tid = threadIdx.x;
    int wid = tid >> 5, lane = tid & 31;
    int wm = (wid & 3) * 32;
    int wn = (wid >> 2) * 64;
    const int rowBase = blockIdx.y * 128;
    const int colBase = blockIdx.x * 128;
    const int nkb = K / 32;

    float acc[2][8][4];
    #pragma unroll
    for (int i = 0; i < 2; i++)
        #pragma unroll
        for (int j = 0; j < 8; j++)
            #pragma unroll
            for (int r = 0; r < 4; r++) acc[i][j][r] = 0.f;

    const int lrow = tid >> 1;
    const int lc = (tid & 1) * 16;

    auto loadTile = [&](int kb, int st) {
        uint32_t db = sb + st * S1_BUF;
        uint32_t doff = lrow * MP_ROWB + lc * 2;
        const __half* pAh = Ah + (size_t)(rowBase + lrow) * K + kb * 32 + lc;
        const __half* pBh = Bh + (size_t)(colBase + lrow) * K + kb * 32 + lc;
        cp16(db + doff,           pAh);  cp16(db + doff + 16,           pAh + 8);
        cp16(db + MP_TILE + doff, pBh);  cp16(db + MP_TILE + doff + 16, pBh + 8);
    };

    loadTile(0, 0);
    cp_commit();
    loadTile(1, 1);
    cp_commit();

    int st = 0, ld = 2;
    for (int kb = 0; kb < nkb; kb++) {
        if (kb + 1 < nkb) cp_wait1(); else cp_wait0();
        __syncthreads();
        if (kb + 2 < nkb) { loadTile(kb + 2, ld); cp_commit(); }

        uint32_t ab = sb + st * S1_BUF;
        uint32_t hb = ab + MP_TILE;

        #pragma unroll
        for (int kk = 0; kk < 2; kk++) {
            int k0 = kk * 16;
            uint32_t aoff = (uint32_t)(wm + (lane & 15)) * MP_ROWB + (k0 + (lane >> 4) * 8) * 2;
            uint32_t ah[2][4];
            #pragma unroll
            for (int mi = 0; mi < 2; mi++)
                ldx4(ah[mi][0], ah[mi][1], ah[mi][2], ah[mi][3], ab + aoff + mi * 16 * MP_ROWB);

            uint32_t bh[16];
            uint32_t boff = (uint32_t)(wn + ((lane >> 4) * 8) + (lane & 7)) * MP_ROWB
                          + (k0 + ((lane >> 3) & 1) * 8) * 2;
            #pragma unroll
            for (int j = 0; j < 4; j++)
                ldx4(bh[4 * j], bh[4 * j + 1], bh[4 * j + 2], bh[4 * j + 3],
                     hb + boff + (uint32_t)(j * 16) * MP_ROWB);

            #pragma unroll
            for (int mi = 0; mi < 2; mi++)
                #pragma unroll
                for (int ni = 0; ni < 8; ni++)
                    mma_fp16(acc[mi][ni], ah[mi], bh[2 * ni], bh[2 * ni + 1]);
        }
        st = (st == 2) ? 0 : st + 1;
        ld = (ld == 2) ? 0 : ld + 1;
    }

    int g = lane >> 2, t = lane & 3;
    const int seg = colBase >> 10;            // for mode 2
    #pragma unroll
    for (int mi = 0; mi < 2; mi++) {
        #pragma unroll
        for (int ni = 0; ni < 8; ni++) {
            int m = rowBase + wm + mi * 16 + g;
            int n = colBase + wn + ni * 8 + 2 * t;
            float b0 = bias[n], b1 = bias[n + 1];
            float x0 = acc[mi][ni][0] + b0, y0 = acc[mi][ni][1] + b1;
            float x1 = acc[mi][ni][2] + b0, y1 = acc[mi][ni][3] + b1;
            if (mode == 0) {
                size_t o0 = (size_t)m * N + n;
                size_t o1 = (size_t)(m + 8) * N + n;
                *(float2*)&Cf[o0] = make_float2(x0, y0);
                *(float2*)&Cf[o1] = make_float2(x1, y1);
            } else if (mode == 1) {
                if (relu) {
                    x0 = fmaxf(x0, 0.f); y0 = fmaxf(y0, 0.f);
                    x1 = fmaxf(x1, 0.f); y1 = fmaxf(y1, 0.f);
                }
                size_t o0 = (size_t)m * N + n;
                size_t o1 = (size_t)(m + 8) * N + n;
                *(uint32_t*)&Ch[o0] = pk2(__float2half_rn(x0), __float2half_rn(y0));
                *(uint32_t*)&Ch[o1] = pk2(__float2half_rn(x1), __float2half_rn(y1));
            } else {
                int nc = n & 1023;
                size_t o0 = (size_t)m * DD + nc;
                size_t o1 = (size_t)(m + 8) * DD + nc;
                if (seg == 0) {
                    *(uint32_t*)&g_qh[o0] = pk2(__float2half_rn(x0 * 0.125f), __float2half_rn(y0 * 0.125f));
                    *(uint32_t*)&g_qh[o1] = pk2(__float2half_rn(x1 * 0.125f), __float2half_rn(y1 * 0.125f));
                } else if (seg == 1) {
                    *(uint32_t*)&g_kh[o0] = pk2(__float2half_rn(x0), __float2half_rn(y0));
                    *(uint32_t*)&g_kh[o1] = pk2(__float2half_rn(x1), __float2half_rn(y1));
                } else {
                    *(uint32_t*)&g_vh[o0] = pk2(__float2half_rn(x0), __float2half_rn(y0));
                    *(uint32_t*)&g_vh[o1] = pk2(__float2half_rn(x1), __float2half_rn(y1));
                }
            }
        }
    }
}

// ============================ flash attention (fp16 mma, single-plane Q/K/V/P) ============================
// smem: Q (1 tile) + 2 x (K,V) double buffer = 5 tiles
#define FA_STR   72
#define FA_ROWB  144
#define FA_TILE  (128 * FA_ROWB)
#define FA_SMEM  (5 * FA_TILE)

__global__ void __launch_bounds__(256, 1) flash_kernel(
    const __half* __restrict__ Qh,
    const __half* __restrict__ Kh, const __half* __restrict__ Vh,
    __half* __restrict__ Oh)
{
    extern __shared__ char smem[];
    uint32_t sb = smem_u32(smem);
    const int bh = blockIdx.x;
    const int qt = 7 - blockIdx.y;
    const int b = bh >> 4, h = bh & 15;
    const int tid = threadIdx.x, wid = tid >> 5, lane = tid & 31;
    const int g = lane >> 2, t4 = lane & 3;
    const int wq = wid * 16 + g;

    const uint32_t sQh = sb;
    const uint32_t sKV = sb + FA_TILE;
    const size_t colbase = (size_t)h * 64;

    {
        int qrow0 = b * LL + qt * 128;
        int krow0 = b * LL;
        #pragma unroll
        for (int i = 0; i < 4; i++) {
            int ch = tid + i * 256;
            int row = ch >> 3, cc = ch & 7;
            uint32_t so = row * FA_ROWB + cc * 16;
            size_t qo = (size_t)(qrow0 + row) * DD + colbase + cc * 8;
            size_t ko = (size_t)(krow0 + row) * DD + colbase + cc * 8;
            cp16(sQh + so, Qh + qo);
            cp16(sKV + so, Kh + ko);
            cp16(sKV + FA_TILE + so, Vh + ko);
        }
        cp_commit();
    }
    cp_wait0();
    __syncthreads();

    uint32_t qhf[4][4];
    {
        uint32_t arow = (uint32_t)(wid * 16 + (lane & 15)) * FA_ROWB;
        #pragma unroll
        for (int kk = 0; kk < 4; kk++) {
            uint32_t aoff = arow + (kk * 16 + (lane >> 4) * 8) * 2;
            ldx4(qhf[kk][0], qhf[kk][1], qhf[kk][2], qhf[kk][3], sQh + aoff);
        }
    }

    float oacc[8][4];
    #pragma unroll
    for (int i = 0; i < 8; i++)
        #pragma unroll
        for (int j = 0; j < 4; j++) oacc[i][j] = 0.f;
    float m0 = -1e30f, m1 = -1e30f, l0 = 0.f, l1 = 0.f;

    for (int kt = 0; kt <= qt; kt++) {
        int buf = kt & 1;
        __syncthreads();
        if (kt < qt) {
            int krow0 = b * LL + (kt + 1) * 128;
            uint32_t dstK = sKV + (buf ^ 1) * 2 * FA_TILE;
            #pragma unroll
            for (int i = 0; i < 4; i++) {
                int ch = tid + i * 256;
                int row = ch >> 3, cc = ch & 7;
                uint32_t so = row * FA_ROWB + cc * 16;
                size_t ko = (size_t)(krow0 + row) * DD + colbase + cc * 8;
                cp16(dstK + so, Kh + ko);
                cp16(dstK + FA_TILE + so, Vh + ko);
            }
            cp_commit();
            cp_wait1();
        } else {
            cp_wait0();
        }
        __syncthreads();

        uint32_t kb = sKV + buf * 2 * FA_TILE;
        uint32_t vb = kb + FA_TILE;

        float s[16][4];
        #pragma unroll
        for (int i = 0; i < 16; i++)
            #pragma unroll
            for (int j = 0; j < 4; j++) s[i][j] = 0.f;

        #pragma unroll
        for (int kk = 0; kk < 4; kk++) {
            #pragma unroll
            for (int nj = 0; nj < 8; nj++) {
                uint32_t boff = kb + (uint32_t)(nj * 16 + (lane >> 4) * 8 + (lane & 7)) * FA_ROWB
                              + (kk * 16 + ((lane >> 3) & 1) * 8) * 2;
                uint32_t b0, b1, b2, b3;
                ldx4(b0, b1, b2, b3, boff);
                mma_fp16(s[2 * nj],     qhf[kk], b0, b1);
                mma_fp16(s[2 * nj + 1], qhf[kk], b2, b3);
            }
        }

        if (kt == qt) {
            #pragma unroll
            for (int ni = 0; ni < 16; ni++) {
                int cl = ni * 8 + t4 * 2;
                if (cl     > wq)     s[ni][0] = -1e30f;
                if (cl + 1 > wq)     s[ni][1] = -1e30f;
                if (cl     > wq + 8) s[ni][2] = -1e30f;
                if (cl + 1 > wq + 8) s[ni][3] = -1e30f;
            }
        }

        float mx0 = -1e30f, mx1 = -1e30f;
        #pragma unroll
        for (int ni = 0; ni < 16; ni++) {
            mx0 = fmaxf(mx0, fmaxf(s[ni][0], s[ni][1]));
            mx1 = fmaxf(mx1, fmaxf(s[ni][2], s[ni][3]));
        }
        mx0 = fmaxf(mx0, __shfl_xor_sync(0xffffffffu, mx0, 1));
        mx0 = fmaxf(mx0, __shfl_xor_sync(0xffffffffu, mx0, 2));
        mx1 = fmaxf(mx1, __shfl_xor_sync(0xffffffffu, mx1, 1));
        mx1 = fmaxf(mx1, __shfl_xor_sync(0xffffffffu, mx1, 2));
        float nm0 = fmaxf(m0, mx0), nm1 = fmaxf(m1, mx1);
        float f0 = __expf(m0 - nm0), f1 = __expf(m1 - nm1);

        float sum0 = 0.f, sum1 = 0.f;
        #pragma unroll
        for (int ni = 0; ni < 16; ni++) {
            s[ni][0] = __expf(s[ni][0] - nm0);
            s[ni][1] = __expf(s[ni][1] - nm0);
            s[ni][2] = __expf(s[ni][2] - nm1);
            s[ni][3] = __expf(s[ni][3] - nm1);
            sum0 += s[ni][0] + s[ni][1];
            sum1 += s[ni][2] + s[ni][3];
        }
        sum0 += __shfl_xor_sync(0xffffffffu, sum0, 1);
        sum0 += __shfl_xor_sync(0xffffffffu, sum0, 2);
        sum1 += __shfl_xor_sync(0xffffffffu, sum1, 1);
        sum1 += __shfl_xor_sync(0xffffffffu, sum1, 2);
        l0 = l0 * f0 + sum0;
        l1 = l1 * f1 + sum1;
        m0 = nm0; m1 = nm1;

        #pragma unroll
        for (int dj = 0; dj < 8; dj++) {
            oacc[dj][0] *= f0; oacc[dj][1] *= f0;
            oacc[dj][2] *= f1; oacc[dj][3] *= f1;
        }

        #pragma unroll
        for (int kk = 0; kk < 8; kk++) {
            uint32_t ah[4];
            ah[0] = pk2(__float2half_rn(s[2 * kk][0]),     __float2half_rn(s[2 * kk][1]));
            ah[1] = pk2(__float2half_rn(s[2 * kk][2]),     __float2half_rn(s[2 * kk][3]));
            ah[2] = pk2(__float2half_rn(s[2 * kk + 1][0]), __float2half_rn(s[2 * kk + 1][1]));
            ah[3] = pk2(__float2half_rn(s[2 * kk + 1][2]), __float2half_rn(s[2 * kk + 1][3]));

            uint32_t vrow = (uint32_t)(kk * 16 + (lane & 7) + 8 * ((lane >> 3) & 1)) * FA_ROWB;
            #pragma unroll
            for (int dj = 0; dj < 4; dj++) {
                uint32_t r0, r1, r2, r3;
                ldx4t(r0, r1, r2, r3, vb + vrow + (dj * 16 + (lane >> 4) * 8) * 2);
                mma_fp16(oacc[2 * dj],     ah, r0, r1);
                mma_fp16(oacc[2 * dj + 1], ah, r2, r3);
            }
        }
    }

    float i0 = 1.f / l0, i1 = 1.f / l1;
    int q0 = qt * 128 + wq;
    size_t r0o = (size_t)(b * LL + q0) * DD + colbase + t4 * 2;
    size_t r1o = r0o + (size_t)8 * DD;
    #pragma unroll
    for (int dj = 0; dj < 8; dj++) {
        *(uint32_t*)&Oh[r0o + dj * 8] = pk2(__float2half_rn(oacc[dj][0] * i0),
                                            __float2half_rn(oacc[dj][1] * i0));
        *(uint32_t*)&Oh[r1o + dj * 8] = pk2(__float2half_rn(oacc[dj][2] * i1),
                                            __float2half_rn(oacc[dj][3] * i1));
    }
}

// ============================ convAll ============================
__global__ void __launch_bounds__(256) convAll_kernel(
    const float* __restrict__ qkvW, const float* __restrict__ outW,
    const float* __restrict__ w1,   const float* __restrict__ w2)
{
    int bid = blockIdx.x;
    int layer = bid / TILES_PER_LAYER;
    int r = bid % TILES_PER_LAYER;
    const float* src;
    __half* dst;
    int K, N;
    if (r < 3072) {
        src = qkvW + (size_t)layer * DD * D3;
        dst = g_wall + (size_t)layer * LSTRIDE + OFF_QKV;
        K = DD; N = D3;
    } else if (r < 4096) {
        r -= 3072;
        src = outW + (size_t)layer * DD * DD;
        dst = g_wall + (size_t)layer * LSTRIDE + OFF_OUT;
        K = DD; N = DD;
    } else if (r < 8192) {
        r -= 4096;
        src = w1 + (size_t)layer * DD * FF;
        dst = g_wall + (size_t)layer * LSTRIDE + OFF_FFN1;
        K = DD; N = FF;
    } else {
        r -= 8192;
        src = w2 + (size_t)layer * FF * DD;
        dst = g_wall + (size_t)layer * LSTRIDE + OFF_FFN2;
        K = FF; N = DD;
    }
    int ntx = N / 32;
    int nb = (r % ntx) * 32;
    int kb = (r / ntx) * 32;

    __shared__ float tile[32][33];
    int tid = threadIdx.x;
    int tx = tid & 31, ty = tid >> 5;
    #pragma unroll
    for (int q = 0; q < 4; q++)
        tile[ty + 8 * q][tx] = src[(size_t)(kb + ty + 8 * q) * N + nb + tx];
    __syncthreads();
    #pragma unroll
    for (int q = 0; q < 4; q++) {
        int n = nb + ty + 8 * q;
        int k = kb + tx;
        dst[(size_t)n * K + k] = __float2half_rn(tile[tx][ty + 8 * q]);
    }
}

// ---------------- embedding + input proj + posenc (+ single plane) ----------------
__global__ void embed_kernel(const int* __restrict__ card_ids,
                             const int* __restrict__ action_ids,
                             const float* __restrict__ bet,
                             const float* __restrict__ card_tab,
                             const float* __restrict__ action_tab,
                             const float* __restrict__ bet_W,
                             const float* __restrict__ bet_b,
                             const float* __restrict__ in_W,
                             const float* __restrict__ in_b)
{
    int t = blockIdx.x;
    int l = t & (LL - 1);
    __shared__ float tok[48];
    int tid = threadIdx.x;
    if (tid < 16)       tok[tid] = card_tab[card_ids[t] * 16 + tid];
    else if (tid < 32)  tok[tid] = action_tab[action_ids[t] * 16 + (tid - 16)];
    else if (tid < 48)  tok[tid] = bet[t] * bet_W[tid - 32] + bet_b[tid - 32];
    __syncthreads();

    const float cdiv = -9.210340371976184f / 1024.0f;
    for (int d = tid; d < DD; d += 256) {
        float acc = in_b[d];
        #pragma unroll
        for (int c = 0; c < 48; c++) acc += tok[c] * in_W[c * DD + d];
        int j2 = d & ~1;
        float ang = (float)l * expf((float)j2 * cdiv);
        float pe = (d & 1) ? cosf(ang) : sinf(ang);
        float x = acc + pe;
        g_x[t * DD + d] = x;
        g_xh[(size_t)t * DD + d] = __float2half_rn(x);
    }
}

// ---------------- residual add + layernorm (+ optional single plane) ----------------
__global__ void __launch_bounds__(256) ln_kernel(const float* __restrict__ xin,
                                                 const float* __restrict__ delta,
                                                 const float* __restrict__ gamma,
                                                 const float* __restrict__ beta,
                                                 float* __restrict__ out,
                                                 __half* __restrict__ Ch)
{
    int row = blockIdx.x, tid = threadIdx.x, lane = tid & 31, warp = tid >> 5;
    __shared__ float red1[8];
    __shared__ float red2[8];
    __shared__ float stats[2];

    float v[4];
    float s = 0.f, s2 = 0.f;
    #pragma unroll
    for (int r = 0; r < 4; r++) {
        int d = tid + r * 256;
        float x = xin[(size_t)row * DD + d] + delta[(size_t)row * DD + d];
        v[r] = x; s += x; s2 += x * x;
    }
    #pragma unroll
    for (int o = 16; o > 0; o >>= 1) {
        s  += __shfl_xor_sync(0xffffffffu, s, o);
        s2 += __shfl_xor_sync(0xffffffffu, s2, o);
    }
    if (lane == 0) { red1[warp] = s; red2[warp] = s2; }
    __syncthreads();
    if (tid == 0) {
        float a = 0.f, c = 0.f;
        #pragma unroll
        for (int i = 0; i < 8; i++) { a += red1[i]; c += red2[i]; }
        float mu = a * (1.0f / DD);
        float var = c * (1.0f / DD) - mu * mu;
        stats[0] = mu;
        stats[1] = rsqrtf(var + 1e-5f);
    }
    __syncthreads();
    float mu = stats[0], rstd = stats[1];
    #pragma unroll
    for (int r = 0; r < 4; r++) {
        int d = tid + r * 256;
        float y = (v[r] - mu) * rstd * gamma[d] + beta[d];
        out[(size_t)row * DD + d] = y;
        if (Ch) Ch[(size_t)row * DD + d] = __float2half_rn(y);
    }
}

// ---------------- extract x[:, -1] ----------------
__global__ void final_kernel(float* __restrict__ out)
{
    int b = blockIdx.x;
    int d = blockIdx.y * 256 + threadIdx.x;
    out[b * DD + d] = g_x[(size_t)(b * LL + (LL - 1)) * DD + d];
}

// ---------------- host launch ----------------
extern "C" void kernel_launch(void* const* d_in, const int* in_sizes, int n_in,
                              void* d_out, int out_size)
{
    const int*   card_ids   = (const int*)  d_in[0];
    const int*   action_ids = (const int*)  d_in[1];
    const float* bet        = (const float*)d_in[2];
    const float* card_tab   = (const float*)d_in[3];
    const float* action_tab = (const float*)d_in[4];
    const float* bet_W      = (const float*)d_in[5];
    const float* bet_b      = (const float*)d_in[6];
    const float* in_W       = (const float*)d_in[7];
    const float* in_b       = (const float*)d_in[8];
    const float* qkv_W      = (const float*)d_in[9];
    const float* qkv_b      = (const float*)d_in[10];
    const float* out_W      = (const float*)d_in[11];
    const float* out_b      = (const float*)d_in[12];
    const float* ln1_g      = (const float*)d_in[13];
    const float* ln1_b      = (const float*)d_in[14];
    const float* ffn_W1     = (const float*)d_in[15];
    const float* ffn_b1     = (const float*)d_in[16];
    const float* ffn_W2     = (const float*)d_in[17];
    const float* ffn_b2     = (const float*)d_in[18];
    const float* ln2_g      = (const float*)d_in[19];
    const float* ln2_b      = (const float*)d_in[20];

    float *px, *py;
    __half *pxh, *poh, *phh, *pqh, *pkh, *pvh, *pwall;
    cudaGetSymbolAddress((void**)&px,    g_x);
    cudaGetSymbolAddress((void**)&py,    g_y);
    cudaGetSymbolAddress((void**)&pxh,   g_xh);
    cudaGetSymbolAddress((void**)&poh,   g_oh);
    cudaGetSymbolAddress((void**)&phh,   g_hh);
    cudaGetSymbolAddress((void**)&pqh,   g_qh);
    cudaGetSymbolAddress((void**)&pkh,   g_kh);
    cudaGetSymbolAddress((void**)&pvh,   g_vh);
    cudaGetSymbolAddress((void**)&pwall, g_wall);

    static int configured = 0;
    if (!configured) {
        cudaFuncSetAttribute(tgemm_kernel, cudaFuncAttributeMaxDynamicSharedMemorySize, SMEM1);
        cudaFuncSetAttribute(flash_kernel, cudaFuncAttributeMaxDynamicSharedMemorySize, FA_SMEM);
        configured = 1;
    }

    convAll_kernel<<<NLAYER * TILES_PER_LAYER, 256>>>(qkv_W, out_W, ffn_W1, ffn_W2);

    embed_kernel<<<TT, 256>>>(card_ids, action_ids, bet, card_tab, action_tab,
                              bet_W, bet_b, in_W, in_b);

    for (int i = 0; i < NLAYER; i++) {
        __half* wqkv = pwall + (size_t)i * LSTRIDE + OFF_QKV;
        __half* wout = pwall + (size_t)i * LSTRIDE + OFF_OUT;
        __half* wff1 = pwall + (size_t)i * LSTRIDE + OFF_FFN1;
        __half* wff2 = pwall + (size_t)i * LSTRIDE + OFF_FFN2;
        const float* qkvb_i = qkv_b  + (size_t)i * D3;
        const float* outb_i = out_b  + (size_t)i * DD;
        const float* l1g_i  = ln1_g  + (size_t)i * DD;
        const float* l1b_i  = ln1_b  + (size_t)i * DD;
        const float* b1_i   = ffn_b1 + (size_t)i * FF;
        const float* b2_i   = ffn_b2 + (size_t)i * DD;
        const float* l2g_i  = ln2_g  + (size_t)i * DD;
        const float* l2b_i  = ln2_b  + (size_t)i * DD;

        // qkv projection (single A plane) -> Q (x0.125), K, V single fp16 (mode 2)
        tgemm_kernel<<<dim3(D3 / 128, TT / 128), 256, SMEM1>>>(
            pxh, wqkv, qkvb_i, nullptr, nullptr, TT, D3, DD, 0, 2);

        // fused flash attention (single-plane Q/K/V/P) -> O fp16
        flash_kernel<<<dim3(32, 8), 256, FA_SMEM>>>(pqh, pkh, pvh, poh);

        // attn out projection (single A plane) -> fp32 delta (mode 0)
        tgemm_kernel<<<dim3(DD / 128, TT / 128), 256, SMEM1>>>(
            poh, wout, outb_i, py, nullptr, TT, DD, DD, 0, 0);

        // x = LN(x + attn)
        ln_kernel<<<TT, 256>>>(px, py, l1g_i, l1b_i, px, pxh);

        // ffn1 (single A plane, relu) -> hidden single plane (mode 1)
        tgemm_kernel<<<dim3(FF / 128, TT / 128), 256, SMEM1>>>(
            pxh, wff1, b1_i, nullptr, phh, TT, FF, DD, 1, 1);

        // ffn2 (single A plane) -> fp32 delta (mode 0)
        tgemm_kernel<<<dim3(DD / 128, TT / 128), 256, SMEM1>>>(
            phh, wff2, b2_i, py, nullptr, TT, DD, FF, 0, 0);

        // x = LN(x + ffn); last layer: skip dead plane writes
        if (i < NLAYER - 1)
            ln_kernel<<<TT, 256>>>(px, py, l2g_i, l2b_i, px, pxh);
        else
            ln_kernel<<<TT, 256>>>(px, py, l2g_i, l2b_i, px, nullptr);
    }

    final_kernel<<<dim3(BB, DD / 256), 256>>>((float*)d_out);
}